// round 4
// baseline (speedup 1.0000x reference)
#include <cuda_runtime.h>
#include <math.h>

// ---------------- problem constants ----------------
#define TB   2
#define TT   2048
#define TC   2048
#define HD   128
#define NH_Q 16      // R*KVH
#define NH_KV 8
#define MROWS (TB*TT)   // 4096

// ---------------- device scratch (no allocs allowed) ----------------
__device__ float g_Q[(size_t)TB * NH_Q  * TT * HD];  // [B, R*KVH, T, D]
__device__ float g_K[(size_t)TB * NH_KV * TT * HD];  // [B, KVH,   T, D]
__device__ float g_V[(size_t)TB * NH_KV * TT * HD];
__device__ float g_O[(size_t)TB * NH_Q  * TT * HD];  // attention output

// =====================================================================
// GEMM 1: projections.  C[m,n] = sum_k x[m,k] * W[k,n]
// x: [4096, 2048] row-major.  W: [2048, N] row-major.
// Output scattered head-major: out[((b*NH + n/128)*T + t)*128 + n%128]
// SEL: 0 -> g_Q, 1 -> g_K, 2 -> g_V
// =====================================================================
template<int SEL, int NH>
__global__ void __launch_bounds__(256) gemm_proj(const float* __restrict__ A,
                                                 const float* __restrict__ W,
                                                 int N) {
    __shared__ float As[16][132];   // transposed A tile [k][m], padded
    __shared__ float Bs[16][128];

    float* out = (SEL == 0) ? g_Q : (SEL == 1) ? g_K : g_V;

    const int K  = TC;
    const int bn = blockIdx.x * 128;
    const int bm = blockIdx.y * 128;
    const int tid = threadIdx.x;
    const int trow = tid >> 4, tcol = tid & 15;

    float acc[8][8];
#pragma unroll
    for (int i = 0; i < 8; i++)
#pragma unroll
        for (int j = 0; j < 8; j++) acc[i][j] = 0.f;

    for (int k0 = 0; k0 < K; k0 += 16) {
        // A tile: 128 rows x 16 cols = 512 float4
#pragma unroll
        for (int l = 0; l < 2; l++) {
            int pos = tid + l * 256;
            int row = pos >> 2;
            int c4  = pos & 3;
            float4 v = *(const float4*)(A + (size_t)(bm + row) * K + k0 + c4 * 4);
            As[c4 * 4 + 0][row] = v.x;
            As[c4 * 4 + 1][row] = v.y;
            As[c4 * 4 + 2][row] = v.z;
            As[c4 * 4 + 3][row] = v.w;
        }
        // B tile: 16 rows x 128 cols
#pragma unroll
        for (int l = 0; l < 2; l++) {
            int pos = tid + l * 256;
            int row = pos >> 5;
            int c4  = pos & 31;
            *(float4*)(&Bs[row][c4 * 4]) =
                *(const float4*)(W + (size_t)(k0 + row) * N + bn + c4 * 4);
        }
        __syncthreads();
#pragma unroll
        for (int kk = 0; kk < 16; kk++) {
            float a[8], b[8];
            *(float4*)(a)     = *(const float4*)(&As[kk][trow * 8]);
            *(float4*)(a + 4) = *(const float4*)(&As[kk][trow * 8 + 4]);
            *(float4*)(b)     = *(const float4*)(&Bs[kk][tcol * 8]);
            *(float4*)(b + 4) = *(const float4*)(&Bs[kk][tcol * 8 + 4]);
#pragma unroll
            for (int i = 0; i < 8; i++)
#pragma unroll
                for (int j = 0; j < 8; j++)
                    acc[i][j] = fmaf(a[i], b[j], acc[i][j]);
        }
        __syncthreads();
    }

    // epilogue: head-major scatter (BN == 128 == HD so head is fixed per block)
    const int head  = bn >> 7;
    const int dbase = tcol * 8;
#pragma unroll
    for (int i = 0; i < 8; i++) {
        int m = bm + trow * 8 + i;
        int b = m >> 11, t = m & 2047;
        float* dst = out + (((size_t)b * NH + head) * TT + t) * HD + dbase;
        *(float4*)(dst)     = make_float4(acc[i][0], acc[i][1], acc[i][2], acc[i][3]);
        *(float4*)(dst + 4) = make_float4(acc[i][4], acc[i][5], acc[i][6], acc[i][7]);
    }
}

// =====================================================================
// RoPE on g_Q and g_K.  One thread per (row, d-pair).
// ts = 1e6^(d/64), arg = t / ts (fp32 div like the ref), then accurate
// fp64 2*pi range reduction so sinf/cosf stay accurate even under fast-math.
// =====================================================================
__global__ void rope_kernel() {
    const long long ROWS_Q = (long long)TB * NH_Q * TT;   // 65536
    const long long ROWS_K = (long long)TB * NH_KV * TT;  // 32768
    long long gid = (long long)blockIdx.x * blockDim.x + threadIdx.x;
    long long total = (ROWS_Q + ROWS_K) * 64;
    if (gid >= total) return;

    int d = (int)(gid & 63);
    long long r = gid >> 6;
    float* base;
    if (r < ROWS_Q) base = g_Q + r * HD;
    else            base = g_K + (r - ROWS_Q) * HD;
    int t = (int)(r & (TT - 1));   // T-position (layout [.., T, D], ROWS_Q % T == 0)

    double ts_d = pow(1.0e6, (double)d * (1.0 / 64.0));
    float ts = (float)ts_d;
    float arg = __fdiv_rn((float)t, ts);

    // accurate range reduction in double
    double da = (double)arg;
    double n  = rint(da * 0.15915494309189535);          // 1/(2*pi)
    double rr = fma(n, -6.283185307179586, da);
    float rf = (float)rr;
    float s = sinf(rf);
    float c = cosf(rf);

    float u1 = base[d];
    float u2 = base[d + 64];
    base[d]      = u1 * c - u2 * s;
    base[d + 64] = u2 * c + u1 * s;
}

// =====================================================================
// Flash attention, fp32.  BM = BN = 64, 256 threads (16x16, 4x4 S tile,
// 4x8 output tile per thread).  Causal + softcap(50) + online softmax.
// grid: (T/64, B*R*KVH)
// =====================================================================
#define SMEM_ATTN_BYTES ((64*132*2 + 64*68) * 4)

__global__ void __launch_bounds__(256, 2) attn_kernel() {
    extern __shared__ float smem[];
    float* Qs  = smem;              // [64][132]
    float* KVs = Qs + 64 * 132;     // [64][132] (K tile, then reused for V)
    float* Ps  = KVs + 64 * 132;    // [64][68]

    const int i0 = blockIdx.x;
    const int bh = blockIdx.y;               // 0..31  (b*16 + r*8 + h)
    const int b   = bh >> 4;
    const int hkv = bh & 7;

    const float* Qb = g_Q + (size_t)bh * TT * HD;
    const float* Kb = g_K + ((size_t)b * NH_KV + hkv) * TT * HD;
    const float* Vb = g_V + ((size_t)b * NH_KV + hkv) * TT * HD;

    const int tid = threadIdx.x;
    const int tr = tid >> 4, tc = tid & 15;

    // load Q tile (64 x 128)
#pragma unroll
    for (int l = 0; l < 8; l++) {
        int pos = tid + l * 256;
        int row = pos >> 5;
        int c4  = pos & 31;
        *(float4*)(&Qs[row * 132 + c4 * 4]) =
            *(const float4*)(Qb + (size_t)(i0 * 64 + row) * HD + c4 * 4);
    }

    float m_i[4], l_i[4], acc[4][8];
#pragma unroll
    for (int i = 0; i < 4; i++) {
        m_i[i] = -1e30f; l_i[i] = 0.f;
#pragma unroll
        for (int j = 0; j < 8; j++) acc[i][j] = 0.f;
    }

    const float scale  = 0.08838834764831845f;  // rsqrt(128)
    const float invcap = 1.0f / 50.0f;

    for (int j0 = 0; j0 <= i0; j0++) {
        __syncthreads();   // protect KVs (prev iter PV) + Qs first iter
        // load K tile
#pragma unroll
        for (int l = 0; l < 8; l++) {
            int pos = tid + l * 256;
            int row = pos >> 5;
            int c4  = pos & 31;
            *(float4*)(&KVs[row * 132 + c4 * 4]) =
                *(const float4*)(Kb + (size_t)(j0 * 64 + row) * HD + c4 * 4);
        }
        __syncthreads();

        // S = Q K^T  (4x4 per thread)
        float s[4][4];
#pragma unroll
        for (int i = 0; i < 4; i++)
#pragma unroll
            for (int j = 0; j < 4; j++) s[i][j] = 0.f;

#pragma unroll 4
        for (int d4 = 0; d4 < 32; d4++) {
            float4 aq[4], bk[4];
#pragma unroll
            for (int i = 0; i < 4; i++)
                aq[i] = *(const float4*)(&Qs[(tr * 4 + i) * 132 + d4 * 4]);
#pragma unroll
            for (int j = 0; j < 4; j++)
                bk[j] = *(const float4*)(&KVs[(tc * 4 + j) * 132 + d4 * 4]);
#pragma unroll
            for (int i = 0; i < 4; i++)
#pragma unroll
                for (int j = 0; j < 4; j++) {
                    s[i][j] = fmaf(aq[i].x, bk[j].x, s[i][j]);
                    s[i][j] = fmaf(aq[i].y, bk[j].y, s[i][j]);
                    s[i][j] = fmaf(aq[i].z, bk[j].z, s[i][j]);
                    s[i][j] = fmaf(aq[i].w, bk[j].w, s[i][j]);
                }
        }

        // scale + softcap + causal mask + row max
        const int mrow0 = i0 * 64 + tr * 4;
        const int ncol0 = j0 * 64 + tc * 4;
        float red[4];
#pragma unroll
        for (int i = 0; i < 4; i++) {
            float mx = -1e30f;
#pragma unroll
            for (int jj = 0; jj < 4; jj++) {
                float x = s[i][jj] * scale;
                x = 50.0f * tanhf(x * invcap);
                if (ncol0 + jj > mrow0 + i) x = -1e30f;
                s[i][jj] = x;
                mx = fmaxf(mx, x);
            }
            red[i] = mx;
        }
#pragma unroll
        for (int off = 1; off < 16; off <<= 1)
#pragma unroll
            for (int i = 0; i < 4; i++)
                red[i] = fmaxf(red[i], __shfl_xor_sync(0xffffffffu, red[i], off));

        float fcorr[4];
#pragma unroll
        for (int i = 0; i < 4; i++) {
            float mnew = fmaxf(m_i[i], red[i]);
            fcorr[i] = expf(m_i[i] - mnew);
            m_i[i] = mnew;
            float rsum = 0.f;
#pragma unroll
            for (int jj = 0; jj < 4; jj++) {
                float p = expf(s[i][jj] - mnew);
                s[i][jj] = p;
                rsum += p;
            }
            red[i] = rsum;
        }
#pragma unroll
        for (int off = 1; off < 16; off <<= 1)
#pragma unroll
            for (int i = 0; i < 4; i++)
                red[i] += __shfl_xor_sync(0xffffffffu, red[i], off);
#pragma unroll
        for (int i = 0; i < 4; i++) {
            l_i[i] = l_i[i] * fcorr[i] + red[i];
#pragma unroll
            for (int j = 0; j < 8; j++) acc[i][j] *= fcorr[i];
        }

        __syncthreads();   // everyone done reading K tile

        // store P tile, load V tile into the same KVs buffer
#pragma unroll
        for (int i = 0; i < 4; i++)
            *(float4*)(&Ps[(tr * 4 + i) * 68 + tc * 4]) =
                make_float4(s[i][0], s[i][1], s[i][2], s[i][3]);
#pragma unroll
        for (int l = 0; l < 8; l++) {
            int pos = tid + l * 256;
            int row = pos >> 5;
            int c4  = pos & 31;
            *(float4*)(&KVs[row * 132 + c4 * 4]) =
                *(const float4*)(Vb + (size_t)(j0 * 64 + row) * HD + c4 * 4);
        }
        __syncthreads();

        // acc += P @ V
#pragma unroll 4
        for (int kv = 0; kv < 64; kv++) {
            float pr[4];
#pragma unroll
            for (int i = 0; i < 4; i++) pr[i] = Ps[(tr * 4 + i) * 68 + kv];
            float vv[8];
            *(float4*)(vv)     = *(const float4*)(&KVs[kv * 132 + tc * 8]);
            *(float4*)(vv + 4) = *(const float4*)(&KVs[kv * 132 + tc * 8 + 4]);
#pragma unroll
            for (int i = 0; i < 4; i++)
#pragma unroll
                for (int j = 0; j < 8; j++)
                    acc[i][j] = fmaf(pr[i], vv[j], acc[i][j]);
        }
    }

    // epilogue
    float* Ob = g_O + (size_t)bh * TT * HD;
#pragma unroll
    for (int i = 0; i < 4; i++) {
        float inv = 1.0f / l_i[i];
        int row = i0 * 64 + tr * 4 + i;
        float* dst = Ob + (size_t)row * HD + tc * 8;
        *(float4*)(dst)     = make_float4(acc[i][0] * inv, acc[i][1] * inv,
                                          acc[i][2] * inv, acc[i][3] * inv);
        *(float4*)(dst + 4) = make_float4(acc[i][4] * inv, acc[i][5] * inv,
                                          acc[i][6] * inv, acc[i][7] * inv);
    }
}

// =====================================================================
// GEMM 2: output projection.
// A[m, kk] gathered from g_O head-major; W2 = out_kernel [2048, 2048];
// out[m, n] row-major = d_out.
// =====================================================================
__global__ void __launch_bounds__(256) gemm_out(const float* __restrict__ W,
                                                float* __restrict__ out) {
    __shared__ float As[16][132];
    __shared__ float Bs[16][128];

    const int N = TC;
    const int K = NH_Q * HD;   // 2048
    const int bn = blockIdx.x * 128;
    const int bm = blockIdx.y * 128;
    const int tid = threadIdx.x;
    const int trow = tid >> 4, tcol = tid & 15;

    float acc[8][8];
#pragma unroll
    for (int i = 0; i < 8; i++)
#pragma unroll
        for (int j = 0; j < 8; j++) acc[i][j] = 0.f;

    for (int k0 = 0; k0 < K; k0 += 16) {
#pragma unroll
        for (int l = 0; l < 2; l++) {
            int pos = tid + l * 256;
            int row = pos >> 2;
            int c4  = pos & 3;
            int m = bm + row;
            int b = m >> 11, t = m & 2047;
            int kc = k0 + c4 * 4;
            int hh = kc >> 7, d = kc & 127;
            float4 v = *(const float4*)(g_O + (((size_t)b * NH_Q + hh) * TT + t) * HD + d);
            As[c4 * 4 + 0][row] = v.x;
            As[c4 * 4 + 1][row] = v.y;
            As[c4 * 4 + 2][row] = v.z;
            As[c4 * 4 + 3][row] = v.w;
        }
#pragma unroll
        for (int l = 0; l < 2; l++) {
            int pos = tid + l * 256;
            int row = pos >> 5;
            int c4  = pos & 31;
            *(float4*)(&Bs[row][c4 * 4]) =
                *(const float4*)(W + (size_t)(k0 + row) * N + bn + c4 * 4);
        }
        __syncthreads();
#pragma unroll
        for (int kk = 0; kk < 16; kk++) {
            float a[8], bb[8];
            *(float4*)(a)      = *(const float4*)(&As[kk][trow * 8]);
            *(float4*)(a + 4)  = *(const float4*)(&As[kk][trow * 8 + 4]);
            *(float4*)(bb)     = *(const float4*)(&Bs[kk][tcol * 8]);
            *(float4*)(bb + 4) = *(const float4*)(&Bs[kk][tcol * 8 + 4]);
#pragma unroll
            for (int i = 0; i < 8; i++)
#pragma unroll
                for (int j = 0; j < 8; j++)
                    acc[i][j] = fmaf(a[i], bb[j], acc[i][j]);
        }
        __syncthreads();
    }

#pragma unroll
    for (int i = 0; i < 8; i++) {
        int m = bm + trow * 8 + i;
        float* dst = out + (size_t)m * N + bn + tcol * 8;
        *(float4*)(dst)     = make_float4(acc[i][0], acc[i][1], acc[i][2], acc[i][3]);
        *(float4*)(dst + 4) = make_float4(acc[i][4], acc[i][5], acc[i][6], acc[i][7]);
    }
}

// =====================================================================
// host entry
// =====================================================================
extern "C" void kernel_launch(void* const* d_in, const int* in_sizes, int n_in,
                              void* d_out, int out_size) {
    const float* x  = (const float*)d_in[0];
    // d_in[1] = mask (ignored: it is the deterministic causal tril mask)
    const float* qk = (const float*)d_in[2];
    const float* kk = (const float*)d_in[3];
    const float* vk = (const float*)d_in[4];
    const float* ok = (const float*)d_in[5];
    float* out = (float*)d_out;

    // projections
    gemm_proj<0, NH_Q> <<<dim3(16, 32), 256>>>(x, qk, 2048);
    gemm_proj<1, NH_KV><<<dim3(8, 32),  256>>>(x, kk, 1024);
    gemm_proj<2, NH_KV><<<dim3(8, 32),  256>>>(x, vk, 1024);

    // RoPE on Q and K
    {
        long long total = ((long long)TB * NH_Q * TT + (long long)TB * NH_KV * TT) * 64;
        int blocks = (int)((total + 255) / 256);
        rope_kernel<<<blocks, 256>>>();
    }

    // flash attention (needs >48KB dynamic smem)
    cudaFuncSetAttribute(attn_kernel, cudaFuncAttributeMaxDynamicSharedMemorySize,
                         SMEM_ATTN_BYTES);
    attn_kernel<<<dim3(TT / 64, TB * NH_Q), 256, SMEM_ATTN_BYTES>>>();

    // output projection
    gemm_out<<<dim3(16, 32), 256>>>(ok, out);
}

// round 6
// speedup vs baseline: 1.4234x; 1.4234x over previous
#include <cuda_runtime.h>
#include <cuda_bf16.h>
#include <math.h>
#include <stdint.h>

// ---------------- problem constants ----------------
#define TB   2
#define TT   2048
#define TC   2048
#define HD   128
#define NH_Q 16      // R*KVH
#define NH_KV 8

// ---------------- device scratch (no allocs allowed) ----------------
__device__ float g_Q[(size_t)TB * NH_Q  * TT * HD];  // [B, R*KVH, T, D] fp32
__device__ float g_K[(size_t)TB * NH_KV * TT * HD];
__device__ float g_V[(size_t)TB * NH_KV * TT * HD];
__device__ float g_O[(size_t)TB * NH_Q  * TT * HD];  // attention output fp32

// bf16 hi/lo split operands for tensor-core GEMMs
__device__ __nv_bfloat16 g_Xh[(size_t)4096 * 2048];   // x  [m, k]
__device__ __nv_bfloat16 g_Xl[(size_t)4096 * 2048];
__device__ __nv_bfloat16 g_Oh[(size_t)4096 * 2048];   // attn out gathered [m, k]
__device__ __nv_bfloat16 g_Ol[(size_t)4096 * 2048];
// weights transposed to K-major [N, K=2048]
__device__ __nv_bfloat16 g_Wqh[(size_t)2048 * 2048];
__device__ __nv_bfloat16 g_Wql[(size_t)2048 * 2048];
__device__ __nv_bfloat16 g_Wkh[(size_t)1024 * 2048];
__device__ __nv_bfloat16 g_Wkl[(size_t)1024 * 2048];
__device__ __nv_bfloat16 g_Wvh[(size_t)1024 * 2048];
__device__ __nv_bfloat16 g_Wvl[(size_t)1024 * 2048];
__device__ __nv_bfloat16 g_Woh[(size_t)2048 * 2048];
__device__ __nv_bfloat16 g_Wol[(size_t)2048 * 2048];

// ---------------- PTX helpers (sm_100-safe: cp.async / ldmatrix / mma.sync) --
__device__ __forceinline__ uint32_t smem_u32(const void* p) {
    uint32_t a;
    asm("{ .reg .u64 t; cvta.to.shared.u64 t, %1; cvt.u32.u64 %0, t; }"
        : "=r"(a) : "l"(p));
    return a;
}
__device__ __forceinline__ void cp16(uint32_t s, const void* g) {
    asm volatile("cp.async.cg.shared.global [%0], [%1], 16;" :: "r"(s), "l"(g));
}
__device__ __forceinline__ void cp_commit() {
    asm volatile("cp.async.commit_group;" ::: "memory");
}
template<int N> __device__ __forceinline__ void cp_wait() {
    asm volatile("cp.async.wait_group %0;" :: "n"(N) : "memory");
}
__device__ __forceinline__ void ldsm4(uint32_t* d, uint32_t addr) {
    asm volatile("ldmatrix.sync.aligned.m8n8.x4.shared.b16 {%0,%1,%2,%3}, [%4];"
                 : "=r"(d[0]), "=r"(d[1]), "=r"(d[2]), "=r"(d[3]) : "r"(addr));
}
__device__ __forceinline__ void ldsm2(uint32_t* d, uint32_t addr) {
    asm volatile("ldmatrix.sync.aligned.m8n8.x2.shared.b16 {%0,%1}, [%2];"
                 : "=r"(d[0]), "=r"(d[1]) : "r"(addr));
}
__device__ __forceinline__ void mma16816(float* c, const uint32_t* a,
                                         const uint32_t* b) {
    asm volatile(
        "mma.sync.aligned.m16n8k16.row.col.f32.bf16.bf16.f32 "
        "{%0,%1,%2,%3}, {%4,%5,%6,%7}, {%8,%9}, {%0,%1,%2,%3};"
        : "+f"(c[0]), "+f"(c[1]), "+f"(c[2]), "+f"(c[3])
        : "r"(a[0]), "r"(a[1]), "r"(a[2]), "r"(a[3]), "r"(b[0]), "r"(b[1]));
}

// ---------------- conversion kernels ----------------
__global__ void cvt_x(const float* __restrict__ x) {
    size_t i = (size_t)blockIdx.x * 256 + threadIdx.x;   // per float4
    float4 v = ((const float4*)x)[i];
    float f[4] = {v.x, v.y, v.z, v.w};
    __nv_bfloat16 h[4], l[4];
#pragma unroll
    for (int j = 0; j < 4; j++) {
        h[j] = __float2bfloat16(f[j]);
        l[j] = __float2bfloat16(f[j] - __bfloat162float(h[j]));
    }
    __nv_bfloat162 p0, p1, q0, q1;
    p0.x = h[0]; p0.y = h[1]; p1.x = h[2]; p1.y = h[3];
    q0.x = l[0]; q0.y = l[1]; q1.x = l[2]; q1.y = l[3];
    ((__nv_bfloat162*)g_Xh)[i * 2]     = p0;
    ((__nv_bfloat162*)g_Xh)[i * 2 + 1] = p1;
    ((__nv_bfloat162*)g_Xl)[i * 2]     = q0;
    ((__nv_bfloat162*)g_Xl)[i * 2 + 1] = q1;
}

// W [2048, N] fp32 -> WT hi/lo [N, 2048] bf16
template<int WSEL>
__global__ void cvt_wT(const float* __restrict__ W) {
    __shared__ float tile[32][33];
    const int N = (WSEL == 1 || WSEL == 2) ? 1024 : 2048;
    __nv_bfloat16* WTh = (WSEL == 0) ? g_Wqh : (WSEL == 1) ? g_Wkh :
                         (WSEL == 2) ? g_Wvh : g_Woh;
    __nv_bfloat16* WTl = (WSEL == 0) ? g_Wql : (WSEL == 1) ? g_Wkl :
                         (WSEL == 2) ? g_Wvl : g_Wol;
    int nb = blockIdx.x * 32, kb = blockIdx.y * 32;
    int tx = threadIdx.x & 31, ty = threadIdx.x >> 5;
#pragma unroll
    for (int r = 0; r < 32; r += 8)
        tile[ty + r][tx] = W[(size_t)(kb + ty + r) * N + nb + tx];
    __syncthreads();
#pragma unroll
    for (int r = 0; r < 32; r += 8) {
        int n = nb + ty + r, k = kb + tx;
        float v = tile[tx][ty + r];
        __nv_bfloat16 h = __float2bfloat16(v);
        __nv_bfloat16 lo = __float2bfloat16(v - __bfloat162float(h));
        WTh[(size_t)n * 2048 + k] = h;
        WTl[(size_t)n * 2048 + k] = lo;
    }
}

// g_O [b,h,t,d] fp32 -> g_Oh/g_Ol [m = b*T+t, k = h*128+d] bf16
__global__ void cvt_o() {
    size_t gid = (size_t)blockIdx.x * 256 + threadIdx.x;  // per 4 elems
    int k4 = (int)(gid & 511);
    int m  = (int)(gid >> 9);
    int b = m >> 11, t = m & 2047;
    int k = k4 * 4, h = k >> 7, d = k & 127;
    float4 v = *(const float4*)(g_O + (((size_t)b * NH_Q + h) * TT + t) * HD + d);
    float f[4] = {v.x, v.y, v.z, v.w};
    __nv_bfloat16 hh[4], ll[4];
#pragma unroll
    for (int j = 0; j < 4; j++) {
        hh[j] = __float2bfloat16(f[j]);
        ll[j] = __float2bfloat16(f[j] - __bfloat162float(hh[j]));
    }
    size_t o = (size_t)m * 2048 + k;
    __nv_bfloat162 p0, p1, q0, q1;
    p0.x = hh[0]; p0.y = hh[1]; p1.x = hh[2]; p1.y = hh[3];
    q0.x = ll[0]; q0.y = ll[1]; q1.x = ll[2]; q1.y = ll[3];
    ((__nv_bfloat162*)(g_Oh + o))[0] = p0;
    ((__nv_bfloat162*)(g_Oh + o))[1] = p1;
    ((__nv_bfloat162*)(g_Ol + o))[0] = q0;
    ((__nv_bfloat162*)(g_Ol + o))[1] = q1;
}

// ---------------- mma.sync bf16-split GEMM ----------------
// C = (Ah+Al)(Bh+Bl)^T ~= Ah Bh^T + Ah Bl^T + Al Bh^T   (fp32 accum)
// A: [M,2048] K-major bf16, B: [N,2048] K-major bf16.
// SEL: 0 -> g_Q, 1 -> g_K, 2 -> g_V (head-major scatter), 3 -> outp row-major.
//
// CTA tile 128x128, BK=32, 8 warps (2x4), warp tile 64x32.
// Smem stage: 4 operand tiles of 128 rows x 80B (32 bf16 + 8 pad) = 40960 B.
#define ROWB     80
#define OPB      10240
#define STAGEB   40960
#define SMEM_GEMM (2 * STAGEB)

__device__ __forceinline__ void load_stage(uint32_t sb,
        const __nv_bfloat16* __restrict__ Ah, const __nv_bfloat16* __restrict__ Al,
        const __nv_bfloat16* __restrict__ Bh, const __nv_bfloat16* __restrict__ Bl,
        int bm, int bn, int k0, int tid) {
#pragma unroll
    for (int j = 0; j < 2; j++) {
        int idx = tid * 2 + j;              // 0..511
        int r = idx >> 2, c = idx & 3;      // row 0..127, 16B chunk 0..3
        uint32_t so = (uint32_t)r * ROWB + (uint32_t)c * 16u;
        size_t ga = (size_t)(bm + r) * 2048 + k0 + c * 8;
        size_t gb = (size_t)(bn + r) * 2048 + k0 + c * 8;
        cp16(sb +            so, Ah + ga);
        cp16(sb + OPB      + so, Al + ga);
        cp16(sb + 2 * OPB  + so, Bh + gb);
        cp16(sb + 3 * OPB  + so, Bl + gb);
    }
}

template<int SEL>
__global__ void __launch_bounds__(256) gemm_bf16(float* __restrict__ outp) {
    extern __shared__ __align__(128) char dsm[];
    const uint32_t smem0 = smem_u32(dsm);

    const __nv_bfloat16 *Ah, *Al, *Bh, *Bl;
    if (SEL == 3)      { Ah = g_Oh; Al = g_Ol; Bh = g_Woh; Bl = g_Wol; }
    else if (SEL == 0) { Ah = g_Xh; Al = g_Xl; Bh = g_Wqh; Bl = g_Wql; }
    else if (SEL == 1) { Ah = g_Xh; Al = g_Xl; Bh = g_Wkh; Bl = g_Wkl; }
    else               { Ah = g_Xh; Al = g_Xl; Bh = g_Wvh; Bl = g_Wvl; }

    const int tid = threadIdx.x;
    const int lid = tid & 31;
    const int wid = tid >> 5;
    const int wm = wid >> 2;        // 0..1
    const int wn = wid & 3;         // 0..3
    const int bn = blockIdx.x * 128;
    const int bm = blockIdx.y * 128;

    // per-lane ldmatrix offsets (bytes)
    const int r8 = lid & 7, gq = lid >> 3;
    const uint32_t aoff = (uint32_t)((gq & 1) * 8 + r8) * ROWB +
                          (uint32_t)(gq >> 1) * 16u + (uint32_t)wm * 64u * ROWB;
    const int lb = lid & 15;
    const uint32_t boff = (uint32_t)(lb & 7) * ROWB +
                          (uint32_t)(lb >> 3) * 16u + (uint32_t)wn * 32u * ROWB;

    float acc[4][4][4];
#pragma unroll
    for (int i = 0; i < 4; i++)
#pragma unroll
        for (int j = 0; j < 4; j++)
#pragma unroll
            for (int k = 0; k < 4; k++) acc[i][j][k] = 0.f;

    load_stage(smem0, Ah, Al, Bh, Bl, bm, bn, 0, tid);
    cp_commit();

    for (int i = 0; i < 64; i++) {
        if (i + 1 < 64) {
            load_stage(smem0 + ((i + 1) & 1) * STAGEB, Ah, Al, Bh, Bl,
                       bm, bn, (i + 1) * 32, tid);
            cp_commit();
            cp_wait<1>();
        } else {
            cp_wait<0>();
        }
        __syncthreads();

        const uint32_t sb = smem0 + (i & 1) * STAGEB;
#pragma unroll
        for (int kk = 0; kk < 2; kk++) {         // two k16 steps (32B apart)
            uint32_t ah[4][4], al[4][4], bh[4][2], bl[4][2];
#pragma unroll
            for (int mt = 0; mt < 4; mt++) {
                uint32_t base = sb + aoff + mt * (16 * ROWB) + kk * 32;
                ldsm4(ah[mt], base);
                ldsm4(al[mt], base + OPB);
            }
#pragma unroll
            for (int nt = 0; nt < 4; nt++) {
                uint32_t base = sb + 2 * OPB + boff + nt * (8 * ROWB) + kk * 32;
                ldsm2(bh[nt], base);
                ldsm2(bl[nt], base + OPB);
            }
#pragma unroll
            for (int mt = 0; mt < 4; mt++)
#pragma unroll
                for (int nt = 0; nt < 4; nt++) {
                    mma16816(acc[mt][nt], ah[mt], bh[nt]);
                    mma16816(acc[mt][nt], ah[mt], bl[nt]);
                    mma16816(acc[mt][nt], al[mt], bh[nt]);
                }
        }
        __syncthreads();
    }

    // epilogue: fragment (c0,c1)->(m, n..n+1), (c2,c3)->(m+8, n..n+1)
    const int t4 = lid >> 2, t2 = (lid & 3) << 1;
    const int head = bn >> 7;           // BN == HD for SEL 0..2
#pragma unroll
    for (int mt = 0; mt < 4; mt++) {
        int m0 = bm + wm * 64 + mt * 16 + t4;
#pragma unroll
        for (int half = 0; half < 2; half++) {
            int m = m0 + half * 8;
            float* dst;
            if (SEL == 3) {
                dst = outp + (size_t)m * 2048 + bn;
            } else {
                int b = m >> 11, t = m & 2047;
                float* base = (SEL == 0) ? g_Q : (SEL == 1) ? g_K : g_V;
                int NHs = (SEL == 0) ? NH_Q : NH_KV;
                dst = base + (((size_t)b * NHs + head) * TT + t) * HD;
            }
#pragma unroll
            for (int nt = 0; nt < 4; nt++) {
                int col = wn * 32 + nt * 8 + t2;
                *(float2*)(dst + col) =
                    make_float2(acc[mt][nt][half * 2], acc[mt][nt][half * 2 + 1]);
            }
        }
    }
}

// =====================================================================
// RoPE on g_Q and g_K (unchanged, known correct)
// =====================================================================
__global__ void rope_kernel() {
    const long long ROWS_Q = (long long)TB * NH_Q * TT;   // 65536
    const long long ROWS_K = (long long)TB * NH_KV * TT;  // 32768
    long long gid = (long long)blockIdx.x * blockDim.x + threadIdx.x;
    long long total = (ROWS_Q + ROWS_K) * 64;
    if (gid >= total) return;

    int d = (int)(gid & 63);
    long long r = gid >> 6;
    float* base;
    if (r < ROWS_Q) base = g_Q + r * HD;
    else            base = g_K + (r - ROWS_Q) * HD;
    int t = (int)(r & (TT - 1));

    double ts_d = pow(1.0e6, (double)d * (1.0 / 64.0));
    float ts = (float)ts_d;
    float arg = __fdiv_rn((float)t, ts);

    double da = (double)arg;
    double n  = rint(da * 0.15915494309189535);
    double rr = fma(n, -6.283185307179586, da);
    float rf = (float)rr;
    float s = sinf(rf);
    float c = cosf(rf);

    float u1 = base[d];
    float u2 = base[d + 64];
    base[d]      = u1 * c - u2 * s;
    base[d + 64] = u2 * c + u1 * s;
}

// =====================================================================
// Flash attention, fp32 (unchanged math; heavy blocks launched first)
// =====================================================================
#define SMEM_ATTN_BYTES ((64*132*2 + 64*68) * 4)

__global__ void __launch_bounds__(256, 2) attn_kernel() {
    extern __shared__ float smem[];
    float* Qs  = smem;              // [64][132]
    float* KVs = Qs + 64 * 132;     // [64][132]
    float* Ps  = KVs + 64 * 132;    // [64][68]

    const int i0 = gridDim.x - 1 - blockIdx.x;   // heavy tiles first
    const int bh = blockIdx.y;
    const int b   = bh >> 4;
    const int hkv = bh & 7;

    const float* Qb = g_Q + (size_t)bh * TT * HD;
    const float* Kb = g_K + ((size_t)b * NH_KV + hkv) * TT * HD;
    const float* Vb = g_V + ((size_t)b * NH_KV + hkv) * TT * HD;

    const int tid = threadIdx.x;
    const int tr = tid >> 4, tc = tid & 15;

#pragma unroll
    for (int l = 0; l < 8; l++) {
        int pos = tid + l * 256;
        int row = pos >> 5;
        int c4  = pos & 31;
        *(float4*)(&Qs[row * 132 + c4 * 4]) =
            *(const float4*)(Qb + (size_t)(i0 * 64 + row) * HD + c4 * 4);
    }

    float m_i[4], l_i[4], acc[4][8];
#pragma unroll
    for (int i = 0; i < 4; i++) {
        m_i[i] = -1e30f; l_i[i] = 0.f;
#pragma unroll
        for (int j = 0; j < 8; j++) acc[i][j] = 0.f;
    }

    const float scale  = 0.08838834764831845f;
    const float invcap = 1.0f / 50.0f;

    for (int j0 = 0; j0 <= i0; j0++) {
        __syncthreads();
#pragma unroll
        for (int l = 0; l < 8; l++) {
            int pos = tid + l * 256;
            int row = pos >> 5;
            int c4  = pos & 31;
            *(float4*)(&KVs[row * 132 + c4 * 4]) =
                *(const float4*)(Kb + (size_t)(j0 * 64 + row) * HD + c4 * 4);
        }
        __syncthreads();

        float s[4][4];
#pragma unroll
        for (int i = 0; i < 4; i++)
#pragma unroll
            for (int j = 0; j < 4; j++) s[i][j] = 0.f;

#pragma unroll 4
        for (int d4 = 0; d4 < 32; d4++) {
            float4 aq[4], bk[4];
#pragma unroll
            for (int i = 0; i < 4; i++)
                aq[i] = *(const float4*)(&Qs[(tr * 4 + i) * 132 + d4 * 4]);
#pragma unroll
            for (int j = 0; j < 4; j++)
                bk[j] = *(const float4*)(&KVs[(tc * 4 + j) * 132 + d4 * 4]);
#pragma unroll
            for (int i = 0; i < 4; i++)
#pragma unroll
                for (int j = 0; j < 4; j++) {
                    s[i][j] = fmaf(aq[i].x, bk[j].x, s[i][j]);
                    s[i][j] = fmaf(aq[i].y, bk[j].y, s[i][j]);
                    s[i][j] = fmaf(aq[i].z, bk[j].z, s[i][j]);
                    s[i][j] = fmaf(aq[i].w, bk[j].w, s[i][j]);
                }
        }

        const int mrow0 = i0 * 64 + tr * 4;
        const int ncol0 = j0 * 64 + tc * 4;
        float red[4];
#pragma unroll
        for (int i = 0; i < 4; i++) {
            float mx = -1e30f;
#pragma unroll
            for (int jj = 0; jj < 4; jj++) {
                float x = s[i][jj] * scale;
                x = 50.0f * tanhf(x * invcap);
                if (ncol0 + jj > mrow0 + i) x = -1e30f;
                s[i][jj] = x;
                mx = fmaxf(mx, x);
            }
            red[i] = mx;
        }
#pragma unroll
        for (int off = 1; off < 16; off <<= 1)
#pragma unroll
            for (int i = 0; i < 4; i++)
                red[i] = fmaxf(red[i], __shfl_xor_sync(0xffffffffu, red[i], off));

        float fcorr[4];
#pragma unroll
        for (int i = 0; i < 4; i++) {
            float mnew = fmaxf(m_i[i], red[i]);
            fcorr[i] = expf(m_i[i] - mnew);
            m_i[i] = mnew;
            float rsum = 0.f;
#pragma unroll
            for (int jj = 0; jj < 4; jj++) {
                float p = expf(s[i][jj] - mnew);
                s[i][jj] = p;
                rsum += p;
            }
            red[i] = rsum;
        }
#pragma unroll
        for (int off = 1; off < 16; off <<= 1)
#pragma unroll
            for (int i = 0; i < 4; i++)
                red[i] += __shfl_xor_sync(0xffffffffu, red[i], off);
#pragma unroll
        for (int i = 0; i < 4; i++) {
            l_i[i] = l_i[i] * fcorr[i] + red[i];
#pragma unroll
            for (int j = 0; j < 8; j++) acc[i][j] *= fcorr[i];
        }

        __syncthreads();

#pragma unroll
        for (int i = 0; i < 4; i++)
            *(float4*)(&Ps[(tr * 4 + i) * 68 + tc * 4]) =
                make_float4(s[i][0], s[i][1], s[i][2], s[i][3]);
#pragma unroll
        for (int l = 0; l < 8; l++) {
            int pos = tid + l * 256;
            int row = pos >> 5;
            int c4  = pos & 31;
            *(float4*)(&KVs[row * 132 + c4 * 4]) =
                *(const float4*)(Vb + (size_t)(j0 * 64 + row) * HD + c4 * 4);
        }
        __syncthreads();

#pragma unroll 4
        for (int kv = 0; kv < 64; kv++) {
            float pr[4];
#pragma unroll
            for (int i = 0; i < 4; i++) pr[i] = Ps[(tr * 4 + i) * 68 + kv];
            float vv[8];
            *(float4*)(vv)     = *(const float4*)(&KVs[kv * 132 + tc * 8]);
            *(float4*)(vv + 4) = *(const float4*)(&KVs[kv * 132 + tc * 8 + 4]);
#pragma unroll
            for (int i = 0; i < 4; i++)
#pragma unroll
                for (int j = 0; j < 8; j++)
                    acc[i][j] = fmaf(pr[i], vv[j], acc[i][j]);
        }
    }

    float* Ob = g_O + (size_t)bh * TT * HD;
#pragma unroll
    for (int i = 0; i < 4; i++) {
        float inv = 1.0f / l_i[i];
        int row = i0 * 64 + tr * 4 + i;
        float* dst = Ob + (size_t)row * HD + tc * 8;
        *(float4*)(dst)     = make_float4(acc[i][0] * inv, acc[i][1] * inv,
                                          acc[i][2] * inv, acc[i][3] * inv);
        *(float4*)(dst + 4) = make_float4(acc[i][4] * inv, acc[i][5] * inv,
                                          acc[i][6] * inv, acc[i][7] * inv);
    }
}

// =====================================================================
// host entry
// =====================================================================
extern "C" void kernel_launch(void* const* d_in, const int* in_sizes, int n_in,
                              void* d_out, int out_size) {
    const float* x  = (const float*)d_in[0];
    // d_in[1] = mask (deterministic causal tril -> ignored)
    const float* qk = (const float*)d_in[2];
    const float* kk = (const float*)d_in[3];
    const float* vk = (const float*)d_in[4];
    const float* ok = (const float*)d_in[5];
    float* out = (float*)d_out;

    cudaFuncSetAttribute(gemm_bf16<0>, cudaFuncAttributeMaxDynamicSharedMemorySize, SMEM_GEMM);
    cudaFuncSetAttribute(gemm_bf16<1>, cudaFuncAttributeMaxDynamicSharedMemorySize, SMEM_GEMM);
    cudaFuncSetAttribute(gemm_bf16<2>, cudaFuncAttributeMaxDynamicSharedMemorySize, SMEM_GEMM);
    cudaFuncSetAttribute(gemm_bf16<3>, cudaFuncAttributeMaxDynamicSharedMemorySize, SMEM_GEMM);
    cudaFuncSetAttribute(attn_kernel, cudaFuncAttributeMaxDynamicSharedMemorySize, SMEM_ATTN_BYTES);

    // split/convert inputs
    cvt_x<<<8192, 256>>>(x);
    cvt_wT<0><<<dim3(64, 64), 256>>>(qk);
    cvt_wT<1><<<dim3(32, 64), 256>>>(kk);
    cvt_wT<2><<<dim3(32, 64), 256>>>(vk);
    cvt_wT<3><<<dim3(64, 64), 256>>>(ok);

    // tensor-core projections (mma.sync bf16 hi/lo split)
    gemm_bf16<0><<<dim3(16, 32), 256, SMEM_GEMM>>>(nullptr);
    gemm_bf16<1><<<dim3(8, 32),  256, SMEM_GEMM>>>(nullptr);
    gemm_bf16<2><<<dim3(8, 32),  256, SMEM_GEMM>>>(nullptr);

    // RoPE
    {
        long long total = ((long long)TB * NH_Q * TT + (long long)TB * NH_KV * TT) * 64;
        int blocks = (int)((total + 255) / 256);
        rope_kernel<<<blocks, 256>>>();
    }

    // attention
    attn_kernel<<<dim3(TT / 64, TB * NH_Q), 256, SMEM_ATTN_BYTES>>>();

    // output projection (tensor cores)
    cvt_o<<<8192, 256>>>();
    gemm_bf16<3><<<dim3(16, 32), 256, SMEM_GEMM>>>(out);
}

// round 7
// speedup vs baseline: 2.8746x; 2.0196x over previous
#include <cuda_runtime.h>
#include <cuda_bf16.h>
#include <math.h>
#include <stdint.h>

// ---------------- problem constants ----------------
#define TB   2
#define TT   2048
#define TC   2048
#define HD   128
#define NH_Q 16      // R*KVH
#define NH_KV 8

// ---------------- device scratch (no allocs allowed) ----------------
__device__ float g_Q[(size_t)TB * NH_Q  * TT * HD];  // fp32 (rope input)
__device__ float g_K[(size_t)TB * NH_KV * TT * HD];

// bf16 hi/lo split operands
__device__ __nv_bfloat16 g_Xh[(size_t)4096 * 2048];   // x  [m, k]
__device__ __nv_bfloat16 g_Xl[(size_t)4096 * 2048];
__device__ __nv_bfloat16 g_Oh[(size_t)4096 * 2048];   // attn out [m, k=h*128+d]
__device__ __nv_bfloat16 g_Ol[(size_t)4096 * 2048];
// rope'd Q/K and V, split, head-major [BH][T][D]
__device__ __nv_bfloat16 g_Qh[(size_t)TB * NH_Q  * TT * HD];
__device__ __nv_bfloat16 g_Ql[(size_t)TB * NH_Q  * TT * HD];
__device__ __nv_bfloat16 g_Kh[(size_t)TB * NH_KV * TT * HD];
__device__ __nv_bfloat16 g_Kl[(size_t)TB * NH_KV * TT * HD];
__device__ __nv_bfloat16 g_Vh[(size_t)TB * NH_KV * TT * HD];
__device__ __nv_bfloat16 g_Vl[(size_t)TB * NH_KV * TT * HD];
// weights transposed to K-major [N, K=2048]
__device__ __nv_bfloat16 g_Wqh[(size_t)2048 * 2048];
__device__ __nv_bfloat16 g_Wql[(size_t)2048 * 2048];
__device__ __nv_bfloat16 g_Wkh[(size_t)1024 * 2048];
__device__ __nv_bfloat16 g_Wkl[(size_t)1024 * 2048];
__device__ __nv_bfloat16 g_Wvh[(size_t)1024 * 2048];
__device__ __nv_bfloat16 g_Wvl[(size_t)1024 * 2048];
__device__ __nv_bfloat16 g_Woh[(size_t)2048 * 2048];
__device__ __nv_bfloat16 g_Wol[(size_t)2048 * 2048];

// ---------------- PTX helpers ----------------
__device__ __forceinline__ uint32_t smem_u32(const void* p) {
    uint32_t a;
    asm("{ .reg .u64 t; cvta.to.shared.u64 t, %1; cvt.u32.u64 %0, t; }"
        : "=r"(a) : "l"(p));
    return a;
}
__device__ __forceinline__ void cp16(uint32_t s, const void* g) {
    asm volatile("cp.async.cg.shared.global [%0], [%1], 16;" :: "r"(s), "l"(g));
}
__device__ __forceinline__ void cp_commit() {
    asm volatile("cp.async.commit_group;" ::: "memory");
}
template<int N> __device__ __forceinline__ void cp_wait() {
    asm volatile("cp.async.wait_group %0;" :: "n"(N) : "memory");
}
__device__ __forceinline__ void ldsm4(uint32_t* d, uint32_t addr) {
    asm volatile("ldmatrix.sync.aligned.m8n8.x4.shared.b16 {%0,%1,%2,%3}, [%4];"
                 : "=r"(d[0]), "=r"(d[1]), "=r"(d[2]), "=r"(d[3]) : "r"(addr));
}
__device__ __forceinline__ void ldsm4t(uint32_t* d, uint32_t addr) {
    asm volatile("ldmatrix.sync.aligned.m8n8.x4.trans.shared.b16 {%0,%1,%2,%3}, [%4];"
                 : "=r"(d[0]), "=r"(d[1]), "=r"(d[2]), "=r"(d[3]) : "r"(addr));
}
__device__ __forceinline__ void ldsm2(uint32_t* d, uint32_t addr) {
    asm volatile("ldmatrix.sync.aligned.m8n8.x2.shared.b16 {%0,%1}, [%2];"
                 : "=r"(d[0]), "=r"(d[1]) : "r"(addr));
}
__device__ __forceinline__ void mma16816(float* c, const uint32_t* a,
                                         const uint32_t* b) {
    asm volatile(
        "mma.sync.aligned.m16n8k16.row.col.f32.bf16.bf16.f32 "
        "{%0,%1,%2,%3}, {%4,%5,%6,%7}, {%8,%9}, {%0,%1,%2,%3};"
        : "+f"(c[0]), "+f"(c[1]), "+f"(c[2]), "+f"(c[3])
        : "r"(a[0]), "r"(a[1]), "r"(a[2]), "r"(a[3]), "r"(b[0]), "r"(b[1]));
}
// pack two floats into bf16x2 hi and residual lo
__device__ __forceinline__ void split2(float a, float b, uint32_t& hi, uint32_t& lo) {
    __nv_bfloat162 h = __floats2bfloat162_rn(a, b);
    float ra = a - __bfloat162float(h.x);
    float rb = b - __bfloat162float(h.y);
    __nv_bfloat162 l = __floats2bfloat162_rn(ra, rb);
    hi = *reinterpret_cast<uint32_t*>(&h);
    lo = *reinterpret_cast<uint32_t*>(&l);
}

// ---------------- conversion kernels ----------------
__global__ void cvt_x(const float* __restrict__ x) {
    size_t i = (size_t)blockIdx.x * 256 + threadIdx.x;   // per float4
    float4 v = ((const float4*)x)[i];
    float f[4] = {v.x, v.y, v.z, v.w};
    uint32_t h0, l0, h1, l1;
    split2(f[0], f[1], h0, l0);
    split2(f[2], f[3], h1, l1);
    ((uint32_t*)g_Xh)[i * 2]     = h0;
    ((uint32_t*)g_Xh)[i * 2 + 1] = h1;
    ((uint32_t*)g_Xl)[i * 2]     = l0;
    ((uint32_t*)g_Xl)[i * 2 + 1] = l1;
}

// W [2048, N] fp32 -> WT hi/lo [N, 2048] bf16
template<int WSEL>
__global__ void cvt_wT(const float* __restrict__ W) {
    __shared__ float tile[32][33];
    const int N = (WSEL == 1 || WSEL == 2) ? 1024 : 2048;
    __nv_bfloat16* WTh = (WSEL == 0) ? g_Wqh : (WSEL == 1) ? g_Wkh :
                         (WSEL == 2) ? g_Wvh : g_Woh;
    __nv_bfloat16* WTl = (WSEL == 0) ? g_Wql : (WSEL == 1) ? g_Wkl :
                         (WSEL == 2) ? g_Wvl : g_Wol;
    int nb = blockIdx.x * 32, kb = blockIdx.y * 32;
    int tx = threadIdx.x & 31, ty = threadIdx.x >> 5;
#pragma unroll
    for (int r = 0; r < 32; r += 8)
        tile[ty + r][tx] = W[(size_t)(kb + ty + r) * N + nb + tx];
    __syncthreads();
#pragma unroll
    for (int r = 0; r < 32; r += 8) {
        int n = nb + ty + r, k = kb + tx;
        float v = tile[tx][ty + r];
        __nv_bfloat16 h = __float2bfloat16(v);
        __nv_bfloat16 lo = __float2bfloat16(v - __bfloat162float(h));
        WTh[(size_t)n * 2048 + k] = h;
        WTl[(size_t)n * 2048 + k] = lo;
    }
}

// ---------------- mma.sync bf16-split GEMM (R6-validated) ----------------
#define ROWB     80
#define OPB      10240
#define STAGEB   40960
#define SMEM_GEMM (2 * STAGEB)

__device__ __forceinline__ void load_stage(uint32_t sb,
        const __nv_bfloat16* __restrict__ Ah, const __nv_bfloat16* __restrict__ Al,
        const __nv_bfloat16* __restrict__ Bh, const __nv_bfloat16* __restrict__ Bl,
        int bm, int bn, int k0, int tid) {
#pragma unroll
    for (int j = 0; j < 2; j++) {
        int idx = tid * 2 + j;
        int r = idx >> 2, c = idx & 3;
        uint32_t so = (uint32_t)r * ROWB + (uint32_t)c * 16u;
        size_t ga = (size_t)(bm + r) * 2048 + k0 + c * 8;
        size_t gb = (size_t)(bn + r) * 2048 + k0 + c * 8;
        cp16(sb +            so, Ah + ga);
        cp16(sb + OPB      + so, Al + ga);
        cp16(sb + 2 * OPB  + so, Bh + gb);
        cp16(sb + 3 * OPB  + so, Bl + gb);
    }
}

template<int SEL>
__global__ void __launch_bounds__(256) gemm_bf16(float* __restrict__ outp) {
    extern __shared__ __align__(128) char dsm[];
    const uint32_t smem0 = smem_u32(dsm);

    const __nv_bfloat16 *Ah, *Al, *Bh, *Bl;
    if (SEL == 3)      { Ah = g_Oh; Al = g_Ol; Bh = g_Woh; Bl = g_Wol; }
    else if (SEL == 0) { Ah = g_Xh; Al = g_Xl; Bh = g_Wqh; Bl = g_Wql; }
    else if (SEL == 1) { Ah = g_Xh; Al = g_Xl; Bh = g_Wkh; Bl = g_Wkl; }
    else               { Ah = g_Xh; Al = g_Xl; Bh = g_Wvh; Bl = g_Wvl; }

    const int tid = threadIdx.x;
    const int lid = tid & 31;
    const int wid = tid >> 5;
    const int wm = wid >> 2;
    const int wn = wid & 3;
    const int bn = blockIdx.x * 128;
    const int bm = blockIdx.y * 128;

    const int r8 = lid & 7, gq = lid >> 3;
    const uint32_t aoff = (uint32_t)((gq & 1) * 8 + r8) * ROWB +
                          (uint32_t)(gq >> 1) * 16u + (uint32_t)wm * 64u * ROWB;
    const int lb = lid & 15;
    const uint32_t boff = (uint32_t)(lb & 7) * ROWB +
                          (uint32_t)(lb >> 3) * 16u + (uint32_t)wn * 32u * ROWB;

    float acc[4][4][4];
#pragma unroll
    for (int i = 0; i < 4; i++)
#pragma unroll
        for (int j = 0; j < 4; j++)
#pragma unroll
            for (int k = 0; k < 4; k++) acc[i][j][k] = 0.f;

    load_stage(smem0, Ah, Al, Bh, Bl, bm, bn, 0, tid);
    cp_commit();

    for (int i = 0; i < 64; i++) {
        if (i + 1 < 64) {
            load_stage(smem0 + ((i + 1) & 1) * STAGEB, Ah, Al, Bh, Bl,
                       bm, bn, (i + 1) * 32, tid);
            cp_commit();
            cp_wait<1>();
        } else {
            cp_wait<0>();
        }
        __syncthreads();

        const uint32_t sb = smem0 + (i & 1) * STAGEB;
#pragma unroll
        for (int kk = 0; kk < 2; kk++) {
            uint32_t ah[4][4], al[4][4], bh[4][2], bl[4][2];
#pragma unroll
            for (int mt = 0; mt < 4; mt++) {
                uint32_t base = sb + aoff + mt * (16 * ROWB) + kk * 32;
                ldsm4(ah[mt], base);
                ldsm4(al[mt], base + OPB);
            }
#pragma unroll
            for (int nt = 0; nt < 4; nt++) {
                uint32_t base = sb + 2 * OPB + boff + nt * (8 * ROWB) + kk * 32;
                ldsm2(bh[nt], base);
                ldsm2(bl[nt], base + OPB);
            }
#pragma unroll
            for (int mt = 0; mt < 4; mt++)
#pragma unroll
                for (int nt = 0; nt < 4; nt++) {
                    mma16816(acc[mt][nt], ah[mt], bh[nt]);
                    mma16816(acc[mt][nt], ah[mt], bl[nt]);
                    mma16816(acc[mt][nt], al[mt], bh[nt]);
                }
        }
        __syncthreads();
    }

    const int t4 = lid >> 2, t2 = (lid & 3) << 1;
    const int head = bn >> 7;
#pragma unroll
    for (int mt = 0; mt < 4; mt++) {
        int m0 = bm + wm * 64 + mt * 16 + t4;
#pragma unroll
        for (int half = 0; half < 2; half++) {
            int m = m0 + half * 8;
            int b = m >> 11, t = m & 2047;
            if (SEL == 2) {
                size_t ro = (((size_t)b * NH_KV + head) * TT + t) * HD;
#pragma unroll
                for (int nt = 0; nt < 4; nt++) {
                    int col = wn * 32 + nt * 8 + t2;
                    uint32_t hi, lo;
                    split2(acc[mt][nt][half * 2], acc[mt][nt][half * 2 + 1], hi, lo);
                    *(uint32_t*)(g_Vh + ro + col) = hi;
                    *(uint32_t*)(g_Vl + ro + col) = lo;
                }
            } else {
                float* dst;
                if (SEL == 3) {
                    dst = outp + (size_t)m * 2048 + bn;
                } else {
                    float* base = (SEL == 0) ? g_Q : g_K;
                    int NHs = (SEL == 0) ? NH_Q : NH_KV;
                    dst = base + (((size_t)b * NHs + head) * TT + t) * HD;
                }
#pragma unroll
                for (int nt = 0; nt < 4; nt++) {
                    int col = wn * 32 + nt * 8 + t2;
                    *(float2*)(dst + col) =
                        make_float2(acc[mt][nt][half * 2], acc[mt][nt][half * 2 + 1]);
                }
            }
        }
    }
}

// =====================================================================
// RoPE: g_Q/g_K fp32 -> rotated bf16 hi/lo (g_Qh/g_Ql/g_Kh/g_Kl)
// =====================================================================
__global__ void rope_split() {
    const long long ROWS_Q = (long long)TB * NH_Q * TT;   // 65536
    const long long ROWS_K = (long long)TB * NH_KV * TT;  // 32768
    long long gid = (long long)blockIdx.x * blockDim.x + threadIdx.x;
    long long total = (ROWS_Q + ROWS_K) * 32;
    if (gid >= total) return;

    int d2 = (int)(gid & 31) * 2;       // 0,2,...,62
    long long r = gid >> 5;
    const float* src;
    __nv_bfloat16 *dh, *dl;
    if (r < ROWS_Q) { src = g_Q + r * HD; dh = g_Qh + r * HD; dl = g_Ql + r * HD; }
    else {
        long long rr = r - ROWS_Q;
        src = g_K + rr * HD; dh = g_Kh + rr * HD; dl = g_Kl + rr * HD;
    }
    int t = (int)(r & (TT - 1));

    float c[2], s[2];
#pragma unroll
    for (int j = 0; j < 2; j++) {
        int d = d2 + j;
        double ts_d = pow(1.0e6, (double)d * (1.0 / 64.0));
        float arg = __fdiv_rn((float)t, (float)ts_d);
        double da = (double)arg;
        double n  = rint(da * 0.15915494309189535);
        double rr2 = fma(n, -6.283185307179586, da);
        float rf = (float)rr2;
        s[j] = sinf(rf);
        c[j] = cosf(rf);
    }
    float u1a = src[d2],      u1b = src[d2 + 1];
    float u2a = src[d2 + 64], u2b = src[d2 + 65];
    float y1a = u1a * c[0] - u2a * s[0], y1b = u1b * c[1] - u2b * s[1];
    float y2a = u2a * c[0] + u1a * s[0], y2b = u2b * c[1] + u1b * s[1];
    uint32_t hi, lo;
    split2(y1a, y1b, hi, lo);
    *(uint32_t*)(dh + d2) = hi;  *(uint32_t*)(dl + d2) = lo;
    split2(y2a, y2b, hi, lo);
    *(uint32_t*)(dh + d2 + 64) = hi;  *(uint32_t*)(dl + d2 + 64) = lo;
}

// =====================================================================
// Flash attention on mma.sync: BM=128, BN=64, 8 warps, 3-term hi/lo.
// =====================================================================
#define ARS   136
#define ARSB  272
#define QSZ   (128 * ARSB)       // 34816 per Q array
#define KVARR (64 * ARSB)        // 17408 per operand array
#define KVSTG (4 * KVARR)        // 69632 per stage (Kh,Kl,Vh,Vl)
#define SMEM_ATTN (2 * QSZ + 2 * KVSTG)   // 208896

__device__ __forceinline__ void load_kv(uint32_t sb,
        const __nv_bfloat16* __restrict__ Khp, const __nv_bfloat16* __restrict__ Klp,
        const __nv_bfloat16* __restrict__ Vhp, const __nv_bfloat16* __restrict__ Vlp,
        int kv0, int tid) {
#pragma unroll
    for (int tpass = 0; tpass < 4; tpass++) {
        int idx = tid + tpass * 256;        // 0..1023
        int r = idx >> 4, cc = idx & 15;
        uint32_t so = (uint32_t)r * ARSB + (uint32_t)cc * 16u;
        size_t go = (size_t)(kv0 + r) * HD + cc * 8;
        cp16(sb +             so, Khp + go);
        cp16(sb + KVARR     + so, Klp + go);
        cp16(sb + 2 * KVARR + so, Vhp + go);
        cp16(sb + 3 * KVARR + so, Vlp + go);
    }
}

__global__ void __launch_bounds__(256, 1) attn_mma() {
    extern __shared__ __align__(128) char asmem[];
    const uint32_t s0  = smem_u32(asmem);
    const uint32_t qhS = s0;
    const uint32_t qlS = s0 + QSZ;
    const uint32_t kvb = s0 + 2 * QSZ;

    const int i0 = gridDim.x - 1 - blockIdx.x;    // heavy blocks first
    const int bh = blockIdx.y;                    // b*16 + h
    const int b  = bh >> 4;
    const int h  = bh & 15;
    const int hkv = h & 7;

    const __nv_bfloat16* Qhp = g_Qh + (size_t)bh * TT * HD;
    const __nv_bfloat16* Qlp = g_Ql + (size_t)bh * TT * HD;
    const size_t kvo = ((size_t)b * NH_KV + hkv) * TT * HD;
    const __nv_bfloat16* Khp = g_Kh + kvo;
    const __nv_bfloat16* Klp = g_Kl + kvo;
    const __nv_bfloat16* Vhp = g_Vh + kvo;
    const __nv_bfloat16* Vlp = g_Vl + kvo;

    const int tid = threadIdx.x, lid = tid & 31, wid = tid >> 5;
    const int t4 = lid >> 2, t2g = lid & 3;
    const int warpRow = wid * 16;

    // fragment smem offsets (within operand array)
    const uint32_t a_off = (uint32_t)(warpRow + (lid & 7) + ((lid >> 3) & 1) * 8) * ARSB +
                           (uint32_t)(lid >> 4) * 16u;
    const uint32_t bk_off = (uint32_t)(lid & 7) * ARSB + (uint32_t)(lid >> 3) * 16u;
    const uint32_t v_off  = (uint32_t)((lid & 7) + ((lid >> 3) & 1) * 8) * ARSB +
                            (uint32_t)(lid >> 4) * 16u;

    // load Q tile (hi+lo)
    {
        int r0q = i0 * 128;
#pragma unroll
        for (int tp = 0; tp < 8; tp++) {
            int idx = tid + tp * 256;       // 0..2047
            int r = idx >> 4, cc = idx & 15;
            uint32_t so = (uint32_t)r * ARSB + (uint32_t)cc * 16u;
            size_t go = (size_t)(r0q + r) * HD + cc * 8;
            cp16(qhS + so, Qhp + go);
            cp16(qlS + so, Qlp + go);
        }
    }
    load_kv(kvb, Khp, Klp, Vhp, Vlp, 0, tid);
    cp_commit();

    float oacc[16][4];
#pragma unroll
    for (int i = 0; i < 16; i++)
#pragma unroll
        for (int j = 0; j < 4; j++) oacc[i][j] = 0.f;
    float mA = -1e30f, mB = -1e30f, lA = 0.f, lB = 0.f;

    const int rowA = i0 * 128 + warpRow + t4;
    const int rowB = rowA + 8;
    const int rowMaxW = i0 * 128 + warpRow + 15;
    const int nj = 2 * i0 + 2;
    const float CS = 0.08838834764831845f / 50.0f;   // rsqrt(128)/softcap

    for (int j = 0; j < nj; j++) {
        if (j + 1 < nj) {
            load_kv(kvb + ((j + 1) & 1) * KVSTG, Khp, Klp, Vhp, Vlp,
                    (j + 1) * 64, tid);
            cp_commit();
            cp_wait<1>();
        } else {
            cp_wait<0>();
        }
        __syncthreads();

        if (j * 64 <= rowMaxW) {           // warp-uniform causal skip
            const uint32_t sb = kvb + (j & 1) * KVSTG;

            // ---- S = Q K^T (3-term) ----
            float sa[8][4];
#pragma unroll
            for (int nt = 0; nt < 8; nt++)
#pragma unroll
                for (int q = 0; q < 4; q++) sa[nt][q] = 0.f;

#pragma unroll
            for (int kp = 0; kp < 4; kp++) {
                uint32_t q0h[4], q1h[4], q0l[4], q1l[4];
                ldsm4(q0h, qhS + a_off + kp * 64);
                ldsm4(q1h, qhS + a_off + kp * 64 + 32);
                ldsm4(q0l, qlS + a_off + kp * 64);
                ldsm4(q1l, qlS + a_off + kp * 64 + 32);
#pragma unroll
                for (int nt = 0; nt < 8; nt++) {
                    uint32_t kh[4], kl[4];
                    uint32_t ka = sb + bk_off + nt * (8 * ARSB) + kp * 64;
                    ldsm4(kh, ka);
                    ldsm4(kl, ka + KVARR);
                    mma16816(sa[nt], q0h, kh);
                    mma16816(sa[nt], q0l, kh);
                    mma16816(sa[nt], q0h, kl);
                    mma16816(sa[nt], q1h, kh + 2);
                    mma16816(sa[nt], q1l, kh + 2);
                    mma16816(sa[nt], q1h, kl + 2);
                }
            }

            // ---- softcap + mask + online softmax ----
            float mxA = -1e30f, mxB = -1e30f;
#pragma unroll
            for (int nt = 0; nt < 8; nt++) {
                int c0 = j * 64 + nt * 8 + 2 * t2g;
                float v0 = 50.f * tanhf(sa[nt][0] * CS);
                float v1 = 50.f * tanhf(sa[nt][1] * CS);
                float v2 = 50.f * tanhf(sa[nt][2] * CS);
                float v3 = 50.f * tanhf(sa[nt][3] * CS);
                if (c0     > rowA) v0 = -1e30f;
                if (c0 + 1 > rowA) v1 = -1e30f;
                if (c0     > rowB) v2 = -1e30f;
                if (c0 + 1 > rowB) v3 = -1e30f;
                sa[nt][0] = v0; sa[nt][1] = v1; sa[nt][2] = v2; sa[nt][3] = v3;
                mxA = fmaxf(mxA, fmaxf(v0, v1));
                mxB = fmaxf(mxB, fmaxf(v2, v3));
            }
            mxA = fmaxf(mxA, __shfl_xor_sync(0xffffffffu, mxA, 1));
            mxA = fmaxf(mxA, __shfl_xor_sync(0xffffffffu, mxA, 2));
            mxB = fmaxf(mxB, __shfl_xor_sync(0xffffffffu, mxB, 1));
            mxB = fmaxf(mxB, __shfl_xor_sync(0xffffffffu, mxB, 2));

            float mAn = fmaxf(mA, mxA), mBn = fmaxf(mB, mxB);
            float fA = __expf(mA - mAn), fB = __expf(mB - mBn);
            mA = mAn; mB = mBn;

            float sA = 0.f, sB = 0.f;
#pragma unroll
            for (int nt = 0; nt < 8; nt++) {
                float p0 = __expf(sa[nt][0] - mA);
                float p1 = __expf(sa[nt][1] - mA);
                float p2 = __expf(sa[nt][2] - mB);
                float p3 = __expf(sa[nt][3] - mB);
                sa[nt][0] = p0; sa[nt][1] = p1; sa[nt][2] = p2; sa[nt][3] = p3;
                sA += p0 + p1; sB += p2 + p3;
            }
            sA += __shfl_xor_sync(0xffffffffu, sA, 1);
            sA += __shfl_xor_sync(0xffffffffu, sA, 2);
            sB += __shfl_xor_sync(0xffffffffu, sB, 1);
            sB += __shfl_xor_sync(0xffffffffu, sB, 2);
            lA = lA * fA + sA;
            lB = lB * fB + sB;
#pragma unroll
            for (int nt = 0; nt < 16; nt++) {
                oacc[nt][0] *= fA; oacc[nt][1] *= fA;
                oacc[nt][2] *= fB; oacc[nt][3] *= fB;
            }

            // ---- O += P V (3-term, P from registers) ----
#pragma unroll
            for (int ks = 0; ks < 4; ks++) {
                uint32_t pah[4], pal[4];
                split2(sa[2 * ks][0],     sa[2 * ks][1],     pah[0], pal[0]);
                split2(sa[2 * ks][2],     sa[2 * ks][3],     pah[1], pal[1]);
                split2(sa[2 * ks + 1][0], sa[2 * ks + 1][1], pah[2], pal[2]);
                split2(sa[2 * ks + 1][2], sa[2 * ks + 1][3], pah[3], pal[3]);
#pragma unroll
                for (int ntp = 0; ntp < 8; ntp++) {
                    uint32_t vh[4], vl[4];
                    uint32_t va = sb + 2 * KVARR + v_off + ks * (16 * ARSB) + ntp * 32;
                    ldsm4t(vh, va);
                    ldsm4t(vl, va + KVARR);
                    mma16816(oacc[2 * ntp],     pah, vh);
                    mma16816(oacc[2 * ntp],     pal, vh);
                    mma16816(oacc[2 * ntp],     pah, vl);
                    mma16816(oacc[2 * ntp + 1], pah, vh + 2);
                    mma16816(oacc[2 * ntp + 1], pal, vh + 2);
                    mma16816(oacc[2 * ntp + 1], pah, vl + 2);
                }
            }
        }
        __syncthreads();
    }

    // ---- epilogue: normalize, split, write g_Oh/g_Ol [m][h*128+d] ----
    float invA = 1.f / lA, invB = 1.f / lB;
    size_t mAr = (size_t)b * 2048 + (size_t)rowA;   // rowA is global t
    size_t mBr = mAr + 8;
    int colbase = h * 128 + 2 * t2g;
#pragma unroll
    for (int nt = 0; nt < 16; nt++) {
        int c = colbase + nt * 8;
        uint32_t hi, lo;
        split2(oacc[nt][0] * invA, oacc[nt][1] * invA, hi, lo);
        *(uint32_t*)(g_Oh + mAr * 2048 + c) = hi;
        *(uint32_t*)(g_Ol + mAr * 2048 + c) = lo;
        split2(oacc[nt][2] * invB, oacc[nt][3] * invB, hi, lo);
        *(uint32_t*)(g_Oh + mBr * 2048 + c) = hi;
        *(uint32_t*)(g_Ol + mBr * 2048 + c) = lo;
    }
}

// =====================================================================
// host entry
// =====================================================================
extern "C" void kernel_launch(void* const* d_in, const int* in_sizes, int n_in,
                              void* d_out, int out_size) {
    const float* x  = (const float*)d_in[0];
    // d_in[1] = mask (deterministic causal tril -> ignored)
    const float* qk = (const float*)d_in[2];
    const float* kk = (const float*)d_in[3];
    const float* vk = (const float*)d_in[4];
    const float* ok = (const float*)d_in[5];
    float* out = (float*)d_out;

    cudaFuncSetAttribute(gemm_bf16<0>, cudaFuncAttributeMaxDynamicSharedMemorySize, SMEM_GEMM);
    cudaFuncSetAttribute(gemm_bf16<1>, cudaFuncAttributeMaxDynamicSharedMemorySize, SMEM_GEMM);
    cudaFuncSetAttribute(gemm_bf16<2>, cudaFuncAttributeMaxDynamicSharedMemorySize, SMEM_GEMM);
    cudaFuncSetAttribute(gemm_bf16<3>, cudaFuncAttributeMaxDynamicSharedMemorySize, SMEM_GEMM);
    cudaFuncSetAttribute(attn_mma, cudaFuncAttributeMaxDynamicSharedMemorySize, SMEM_ATTN);

    // split/convert inputs
    cvt_x<<<8192, 256>>>(x);
    cvt_wT<0><<<dim3(64, 64), 256>>>(qk);
    cvt_wT<1><<<dim3(32, 64), 256>>>(kk);
    cvt_wT<2><<<dim3(32, 64), 256>>>(vk);
    cvt_wT<3><<<dim3(64, 64), 256>>>(ok);

    // projections (Q,K fp32 for rope; V split bf16 directly)
    gemm_bf16<0><<<dim3(16, 32), 256, SMEM_GEMM>>>(nullptr);
    gemm_bf16<1><<<dim3(8, 32),  256, SMEM_GEMM>>>(nullptr);
    gemm_bf16<2><<<dim3(8, 32),  256, SMEM_GEMM>>>(nullptr);

    // RoPE -> bf16 hi/lo Q/K
    {
        long long total = ((long long)TB * NH_Q * TT + (long long)TB * NH_KV * TT) * 32;
        int blocks = (int)((total + 255) / 256);
        rope_split<<<blocks, 256>>>();
    }

    // tensor-core flash attention (writes g_Oh/g_Ol)
    attn_mma<<<dim3(TT / 128, TB * NH_Q), 256, SMEM_ATTN>>>();

    // output projection
    gemm_bf16<3><<<dim3(16, 32), 256, SMEM_GEMM>>>(out);
}

// round 8
// speedup vs baseline: 4.3560x; 1.5153x over previous
#include <cuda_runtime.h>
#include <cuda_fp16.h>
#include <math.h>
#include <stdint.h>

// ---------------- problem constants ----------------
#define TB   2
#define TT   2048
#define TC   2048
#define HD   128
#define NH_Q 16      // R*KVH
#define NH_KV 8

// ---------------- device scratch (no allocs allowed) ----------------
__device__ float g_Q[(size_t)TB * NH_Q  * TT * HD];  // fp32 (rope input)
__device__ float g_K[(size_t)TB * NH_KV * TT * HD];

// fp16 operands
__device__ __half g_Xh[(size_t)4096 * 2048];   // x hi  [m, k]
__device__ __half g_Xl[(size_t)4096 * 2048];   // x lo
__device__ __half g_Oh[(size_t)4096 * 2048];   // attn out hi [m, k=h*128+d]
__device__ __half g_Ol[(size_t)4096 * 2048];   // attn out lo
// rope'd Q (split) / K (single) and V (single), head-major [BH][T][D]
__device__ __half g_Qh[(size_t)TB * NH_Q  * TT * HD];
__device__ __half g_Ql[(size_t)TB * NH_Q  * TT * HD];
__device__ __half g_Kh[(size_t)TB * NH_KV * TT * HD];
__device__ __half g_Vh[(size_t)TB * NH_KV * TT * HD];
// weights transposed to K-major [N, K=2048], single fp16
__device__ __half g_Wq[(size_t)2048 * 2048];
__device__ __half g_Wk[(size_t)1024 * 2048];
__device__ __half g_Wv[(size_t)1024 * 2048];
__device__ __half g_Wo[(size_t)2048 * 2048];

// ---------------- PTX helpers ----------------
__device__ __forceinline__ uint32_t smem_u32(const void* p) {
    uint32_t a;
    asm("{ .reg .u64 t; cvta.to.shared.u64 t, %1; cvt.u32.u64 %0, t; }"
        : "=r"(a) : "l"(p));
    return a;
}
__device__ __forceinline__ void cp16(uint32_t s, const void* g) {
    asm volatile("cp.async.cg.shared.global [%0], [%1], 16;" :: "r"(s), "l"(g));
}
__device__ __forceinline__ void cp_commit() {
    asm volatile("cp.async.commit_group;" ::: "memory");
}
template<int N> __device__ __forceinline__ void cp_wait() {
    asm volatile("cp.async.wait_group %0;" :: "n"(N) : "memory");
}
__device__ __forceinline__ void ldsm4(uint32_t* d, uint32_t addr) {
    asm volatile("ldmatrix.sync.aligned.m8n8.x4.shared.b16 {%0,%1,%2,%3}, [%4];"
                 : "=r"(d[0]), "=r"(d[1]), "=r"(d[2]), "=r"(d[3]) : "r"(addr));
}
__device__ __forceinline__ void ldsm4t(uint32_t* d, uint32_t addr) {
    asm volatile("ldmatrix.sync.aligned.m8n8.x4.trans.shared.b16 {%0,%1,%2,%3}, [%4];"
                 : "=r"(d[0]), "=r"(d[1]), "=r"(d[2]), "=r"(d[3]) : "r"(addr));
}
__device__ __forceinline__ void ldsm2(uint32_t* d, uint32_t addr) {
    asm volatile("ldmatrix.sync.aligned.m8n8.x2.shared.b16 {%0,%1}, [%2];"
                 : "=r"(d[0]), "=r"(d[1]) : "r"(addr));
}
__device__ __forceinline__ void mma16816h(float* c, const uint32_t* a,
                                          const uint32_t* b) {
    asm volatile(
        "mma.sync.aligned.m16n8k16.row.col.f32.f16.f16.f32 "
        "{%0,%1,%2,%3}, {%4,%5,%6,%7}, {%8,%9}, {%0,%1,%2,%3};"
        : "+f"(c[0]), "+f"(c[1]), "+f"(c[2]), "+f"(c[3])
        : "r"(a[0]), "r"(a[1]), "r"(a[2]), "r"(a[3]), "r"(b[0]), "r"(b[1]));
}
// pack two floats into fp16x2 hi and residual lo
__device__ __forceinline__ void split2h(float a, float b, uint32_t& hi, uint32_t& lo) {
    __half2 h = __floats2half2_rn(a, b);
    float ra = a - __half2float(h.x);
    float rb = b - __half2float(h.y);
    __half2 l = __floats2half2_rn(ra, rb);
    hi = *reinterpret_cast<uint32_t*>(&h);
    lo = *reinterpret_cast<uint32_t*>(&l);
}
__device__ __forceinline__ uint32_t pack2h(float a, float b) {
    __half2 h = __floats2half2_rn(a, b);
    return *reinterpret_cast<uint32_t*>(&h);
}

// ---------------- conversion kernels ----------------
__global__ void cvt_x(const float* __restrict__ x) {
    size_t i = (size_t)blockIdx.x * 256 + threadIdx.x;   // per float4
    float4 v = ((const float4*)x)[i];
    uint32_t h0, l0, h1, l1;
    split2h(v.x, v.y, h0, l0);
    split2h(v.z, v.w, h1, l1);
    ((uint32_t*)g_Xh)[i * 2]     = h0;
    ((uint32_t*)g_Xh)[i * 2 + 1] = h1;
    ((uint32_t*)g_Xl)[i * 2]     = l0;
    ((uint32_t*)g_Xl)[i * 2 + 1] = l1;
}

// W [2048, N] fp32 -> WT [N, 2048] fp16 (single, rounded)
template<int WSEL>
__global__ void cvt_wT(const float* __restrict__ W) {
    __shared__ float tile[32][33];
    const int N = (WSEL == 1 || WSEL == 2) ? 1024 : 2048;
    __half* WT = (WSEL == 0) ? g_Wq : (WSEL == 1) ? g_Wk :
                 (WSEL == 2) ? g_Wv : g_Wo;
    int nb = blockIdx.x * 32, kb = blockIdx.y * 32;
    int tx = threadIdx.x & 31, ty = threadIdx.x >> 5;
#pragma unroll
    for (int r = 0; r < 32; r += 8)
        tile[ty + r][tx] = W[(size_t)(kb + ty + r) * N + nb + tx];
    __syncthreads();
#pragma unroll
    for (int r = 0; r < 32; r += 8) {
        int n = nb + ty + r, k = kb + tx;
        WT[(size_t)n * 2048 + k] = __float2half_rn(tile[tx][ty + r]);
    }
}

// ---------------- mma.sync fp16 2-term GEMM ----------------
// C = (Ah+Al) * B^T ; A split fp16, B rounded fp16, fp32 accum.
// SEL 0: fused QKV projection (A=x), N-space 4096 = [Q 2048 | K 1024 | V 1024]
// SEL 1: output projection (A=attn out), writes d_out fp32.
#define ROWB     80
#define OPB      10240
#define STAGEB   30720
#define NSTG     3
#define SMEM_GEMM (NSTG * STAGEB)

__device__ __forceinline__ void load_stage(uint32_t sb,
        const __half* __restrict__ Ah, const __half* __restrict__ Al,
        const __half* __restrict__ Bp, int bm, int k0, int tid) {
#pragma unroll
    for (int j = 0; j < 2; j++) {
        int idx = tid * 2 + j;
        int r = idx >> 2, c = idx & 3;
        uint32_t so = (uint32_t)r * ROWB + (uint32_t)c * 16u;
        size_t ga = (size_t)(bm + r) * 2048 + k0 + c * 8;
        size_t gb = (size_t)r * 2048 + k0 + c * 8;
        cp16(sb +           so, Ah + ga);
        cp16(sb + OPB     + so, Al + ga);
        cp16(sb + 2 * OPB + so, Bp + gb);
    }
}

template<int SEL>
__global__ void __launch_bounds__(256) gemm_f16(float* __restrict__ outp) {
    extern __shared__ __align__(128) char dsm[];
    const uint32_t smem0 = smem_u32(dsm);

    const int tid = threadIdx.x;
    const int lid = tid & 31;
    const int wid = tid >> 5;
    const int wm = wid >> 2;
    const int wn = wid & 3;
    const int bn = blockIdx.x * 128;
    const int bm = blockIdx.y * 128;

    const __half *Ah, *Al, *Bp;
    if (SEL == 1) {
        Ah = g_Oh; Al = g_Ol;
        Bp = g_Wo + (size_t)bn * 2048;
    } else {
        Ah = g_Xh; Al = g_Xl;
        if (bn < 2048)      Bp = g_Wq + (size_t)bn * 2048;
        else if (bn < 3072) Bp = g_Wk + (size_t)(bn - 2048) * 2048;
        else                Bp = g_Wv + (size_t)(bn - 3072) * 2048;
    }

    const int r8 = lid & 7, gq = lid >> 3;
    const uint32_t aoff = (uint32_t)((gq & 1) * 8 + r8) * ROWB +
                          (uint32_t)(gq >> 1) * 16u + (uint32_t)wm * 64u * ROWB;
    const int lb = lid & 15;
    const uint32_t boff = (uint32_t)(lb & 7) * ROWB +
                          (uint32_t)(lb >> 3) * 16u + (uint32_t)wn * 32u * ROWB;

    float acc[4][4][4];
#pragma unroll
    for (int i = 0; i < 4; i++)
#pragma unroll
        for (int j = 0; j < 4; j++)
#pragma unroll
            for (int k = 0; k < 4; k++) acc[i][j][k] = 0.f;

    load_stage(smem0, Ah, Al, Bp, bm, 0, tid);
    cp_commit();
    load_stage(smem0 + STAGEB, Ah, Al, Bp, bm, 32, tid);
    cp_commit();

    const int NI = 64;
    int sidx = 0;
    for (int i = 0; i < NI; i++) {
        if (i + 2 < NI) {
            int ns = sidx + 2; if (ns >= NSTG) ns -= NSTG;
            load_stage(smem0 + ns * STAGEB, Ah, Al, Bp, bm, (i + 2) * 32, tid);
            cp_commit();
            cp_wait<2>();
        } else if (i + 1 < NI) {
            cp_wait<1>();
        } else {
            cp_wait<0>();
        }
        __syncthreads();

        const uint32_t sb = smem0 + sidx * STAGEB;
#pragma unroll
        for (int kk = 0; kk < 2; kk++) {
            uint32_t ah[4][4], al[4][4], bf[4][2];
#pragma unroll
            for (int mt = 0; mt < 4; mt++) {
                uint32_t base = sb + aoff + mt * (16 * ROWB) + kk * 32;
                ldsm4(ah[mt], base);
                ldsm4(al[mt], base + OPB);
            }
#pragma unroll
            for (int nt = 0; nt < 4; nt++)
                ldsm2(bf[nt], sb + 2 * OPB + boff + nt * (8 * ROWB) + kk * 32);
#pragma unroll
            for (int mt = 0; mt < 4; mt++)
#pragma unroll
                for (int nt = 0; nt < 4; nt++) {
                    mma16816h(acc[mt][nt], ah[mt], bf[nt]);
                    mma16816h(acc[mt][nt], al[mt], bf[nt]);
                }
        }
        __syncthreads();
        if (++sidx >= NSTG) sidx = 0;
    }

    // epilogue
    const int t4 = lid >> 2, t2 = (lid & 3) << 1;
#pragma unroll
    for (int mt = 0; mt < 4; mt++) {
        int m0 = bm + wm * 64 + mt * 16 + t4;
#pragma unroll
        for (int half = 0; half < 2; half++) {
            int m = m0 + half * 8;
            int b = m >> 11, t = m & 2047;
            if (SEL == 1) {
                float* dst = outp + (size_t)m * 2048 + bn;
#pragma unroll
                for (int nt = 0; nt < 4; nt++) {
                    int col = wn * 32 + nt * 8 + t2;
                    *(float2*)(dst + col) =
                        make_float2(acc[mt][nt][half * 2], acc[mt][nt][half * 2 + 1]);
                }
            } else if (bn < 3072) {
                // Q or K -> fp32 (rope input), head-major
                float* base;
                int head, NHs;
                if (bn < 2048) { base = g_Q; head = bn >> 7; NHs = NH_Q; }
                else           { base = g_K; head = (bn - 2048) >> 7; NHs = NH_KV; }
                float* dst = base + (((size_t)b * NHs + head) * TT + t) * HD;
#pragma unroll
                for (int nt = 0; nt < 4; nt++) {
                    int col = wn * 32 + nt * 8 + t2;
                    *(float2*)(dst + col) =
                        make_float2(acc[mt][nt][half * 2], acc[mt][nt][half * 2 + 1]);
                }
            } else {
                // V -> fp16 single, head-major
                int head = (bn - 3072) >> 7;
                size_t ro = (((size_t)b * NH_KV + head) * TT + t) * HD;
#pragma unroll
                for (int nt = 0; nt < 4; nt++) {
                    int col = wn * 32 + nt * 8 + t2;
                    *(uint32_t*)(g_Vh + ro + col) =
                        pack2h(acc[mt][nt][half * 2], acc[mt][nt][half * 2 + 1]);
                }
            }
        }
    }
}

// =====================================================================
// RoPE: g_Q fp32 -> g_Qh/g_Ql fp16 split;  g_K fp32 -> g_Kh fp16 single
// =====================================================================
__global__ void rope_split() {
    const long long ROWS_Q = (long long)TB * NH_Q * TT;   // 65536
    const long long ROWS_K = (long long)TB * NH_KV * TT;  // 32768
    long long gid = (long long)blockIdx.x * blockDim.x + threadIdx.x;
    long long total = (ROWS_Q + ROWS_K) * 32;
    if (gid >= total) return;

    int d2 = (int)(gid & 31) * 2;       // 0,2,...,62
    long long r = gid >> 5;
    const float* src;
    __half *dh, *dl;
    bool isQ;
    if (r < ROWS_Q) {
        src = g_Q + r * HD; dh = g_Qh + r * HD; dl = g_Ql + r * HD; isQ = true;
    } else {
        long long rr = r - ROWS_Q;
        src = g_K + rr * HD; dh = g_Kh + rr * HD; dl = nullptr; isQ = false;
    }
    int t = (int)(r & (TT - 1));

    float c[2], s[2];
#pragma unroll
    for (int j = 0; j < 2; j++) {
        int d = d2 + j;
        double ts_d = pow(1.0e6, (double)d * (1.0 / 64.0));
        float arg = __fdiv_rn((float)t, (float)ts_d);
        double da = (double)arg;
        double n  = rint(da * 0.15915494309189535);
        double rr2 = fma(n, -6.283185307179586, da);
        float rf = (float)rr2;
        s[j] = sinf(rf);
        c[j] = cosf(rf);
    }
    float u1a = src[d2],      u1b = src[d2 + 1];
    float u2a = src[d2 + 64], u2b = src[d2 + 65];
    float y1a = u1a * c[0] - u2a * s[0], y1b = u1b * c[1] - u2b * s[1];
    float y2a = u2a * c[0] + u1a * s[0], y2b = u2b * c[1] + u1b * s[1];
    if (isQ) {
        uint32_t hi, lo;
        split2h(y1a, y1b, hi, lo);
        *(uint32_t*)(dh + d2) = hi;  *(uint32_t*)(dl + d2) = lo;
        split2h(y2a, y2b, hi, lo);
        *(uint32_t*)(dh + d2 + 64) = hi;  *(uint32_t*)(dl + d2 + 64) = lo;
    } else {
        *(uint32_t*)(dh + d2)      = pack2h(y1a, y1b);
        *(uint32_t*)(dh + d2 + 64) = pack2h(y2a, y2b);
    }
}

// =====================================================================
// Flash attention: BM=128, BN=64, 8 warps.  Q split fp16 (2-term),
// K/V single fp16, P split fp16 (2-term).  fp32 accumulate.
// =====================================================================
#define ARSB  272
#define QSZ   (128 * ARSB)       // 34816 per Q array
#define KVARR (64 * ARSB)        // 17408 per operand array
#define KVSTG (2 * KVARR)        // 34816 per stage (Kh, Vh)
#define SMEM_ATTN (2 * QSZ + 2 * KVSTG)   // 139264

__device__ __forceinline__ void load_kv(uint32_t sb,
        const __half* __restrict__ Khp, const __half* __restrict__ Vhp,
        int kv0, int tid) {
#pragma unroll
    for (int tpass = 0; tpass < 4; tpass++) {
        int idx = tid + tpass * 256;        // 0..1023
        int r = idx >> 4, cc = idx & 15;
        uint32_t so = (uint32_t)r * ARSB + (uint32_t)cc * 16u;
        size_t go = (size_t)(kv0 + r) * HD + cc * 8;
        cp16(sb +         so, Khp + go);
        cp16(sb + KVARR + so, Vhp + go);
    }
}

__global__ void __launch_bounds__(256, 1) attn_mma() {
    extern __shared__ __align__(128) char asmem[];
    const uint32_t s0  = smem_u32(asmem);
    const uint32_t qhS = s0;
    const uint32_t qlS = s0 + QSZ;
    const uint32_t kvb = s0 + 2 * QSZ;

    const int i0 = gridDim.x - 1 - blockIdx.x;    // heavy blocks first
    const int bh = blockIdx.y;                    // b*16 + h
    const int b  = bh >> 4;
    const int h  = bh & 15;
    const int hkv = h & 7;

    const __half* Qhp = g_Qh + (size_t)bh * TT * HD;
    const __half* Qlp = g_Ql + (size_t)bh * TT * HD;
    const size_t kvo = ((size_t)b * NH_KV + hkv) * TT * HD;
    const __half* Khp = g_Kh + kvo;
    const __half* Vhp = g_Vh + kvo;

    const int tid = threadIdx.x, lid = tid & 31, wid = tid >> 5;
    const int t4 = lid >> 2, t2g = lid & 3;
    const int warpRow = wid * 16;

    const uint32_t a_off = (uint32_t)(warpRow + (lid & 7) + ((lid >> 3) & 1) * 8) * ARSB +
                           (uint32_t)(lid >> 4) * 16u;
    const uint32_t bk_off = (uint32_t)(lid & 7) * ARSB + (uint32_t)(lid >> 3) * 16u;
    const uint32_t v_off  = (uint32_t)((lid & 7) + ((lid >> 3) & 1) * 8) * ARSB +
                            (uint32_t)(lid >> 4) * 16u;

    // load Q tile (hi+lo)
    {
        int r0q = i0 * 128;
#pragma unroll
        for (int tp = 0; tp < 8; tp++) {
            int idx = tid + tp * 256;       // 0..2047
            int r = idx >> 4, cc = idx & 15;
            uint32_t so = (uint32_t)r * ARSB + (uint32_t)cc * 16u;
            size_t go = (size_t)(r0q + r) * HD + cc * 8;
            cp16(qhS + so, Qhp + go);
            cp16(qlS + so, Qlp + go);
        }
    }
    load_kv(kvb, Khp, Vhp, 0, tid);
    cp_commit();

    float oacc[16][4];
#pragma unroll
    for (int i = 0; i < 16; i++)
#pragma unroll
        for (int j = 0; j < 4; j++) oacc[i][j] = 0.f;
    float mA = -1e30f, mB = -1e30f, lA = 0.f, lB = 0.f;

    const int rowA = i0 * 128 + warpRow + t4;
    const int rowB = rowA + 8;
    const int rowMaxW = i0 * 128 + warpRow + 15;
    const int nj = 2 * i0 + 2;
    const float CS = 0.08838834764831845f / 50.0f;   // rsqrt(128)/softcap

    for (int j = 0; j < nj; j++) {
        if (j + 1 < nj) {
            load_kv(kvb + ((j + 1) & 1) * KVSTG, Khp, Vhp, (j + 1) * 64, tid);
            cp_commit();
            cp_wait<1>();
        } else {
            cp_wait<0>();
        }
        __syncthreads();

        if (j * 64 <= rowMaxW) {           // warp-uniform causal skip
            const uint32_t sb = kvb + (j & 1) * KVSTG;

            // ---- S = Q K^T (Q 2-term, K single) ----
            float sa[8][4];
#pragma unroll
            for (int nt = 0; nt < 8; nt++)
#pragma unroll
                for (int q = 0; q < 4; q++) sa[nt][q] = 0.f;

#pragma unroll
            for (int kp = 0; kp < 4; kp++) {
                uint32_t q0h[4], q1h[4], q0l[4], q1l[4];
                ldsm4(q0h, qhS + a_off + kp * 64);
                ldsm4(q1h, qhS + a_off + kp * 64 + 32);
                ldsm4(q0l, qlS + a_off + kp * 64);
                ldsm4(q1l, qlS + a_off + kp * 64 + 32);
#pragma unroll
                for (int nt = 0; nt < 8; nt++) {
                    uint32_t kh[4];
                    ldsm4(kh, sb + bk_off + nt * (8 * ARSB) + kp * 64);
                    mma16816h(sa[nt], q0h, kh);
                    mma16816h(sa[nt], q0l, kh);
                    mma16816h(sa[nt], q1h, kh + 2);
                    mma16816h(sa[nt], q1l, kh + 2);
                }
            }

            // ---- softcap + mask + online softmax ----
            float mxA = -1e30f, mxB = -1e30f;
#pragma unroll
            for (int nt = 0; nt < 8; nt++) {
                int c0 = j * 64 + nt * 8 + 2 * t2g;
                float v0 = 50.f * tanhf(sa[nt][0] * CS);
                float v1 = 50.f * tanhf(sa[nt][1] * CS);
                float v2 = 50.f * tanhf(sa[nt][2] * CS);
                float v3 = 50.f * tanhf(sa[nt][3] * CS);
                if (c0     > rowA) v0 = -1e30f;
                if (c0 + 1 > rowA) v1 = -1e30f;
                if (c0     > rowB) v2 = -1e30f;
                if (c0 + 1 > rowB) v3 = -1e30f;
                sa[nt][0] = v0; sa[nt][1] = v1; sa[nt][2] = v2; sa[nt][3] = v3;
                mxA = fmaxf(mxA, fmaxf(v0, v1));
                mxB = fmaxf(mxB, fmaxf(v2, v3));
            }
            mxA = fmaxf(mxA, __shfl_xor_sync(0xffffffffu, mxA, 1));
            mxA = fmaxf(mxA, __shfl_xor_sync(0xffffffffu, mxA, 2));
            mxB = fmaxf(mxB, __shfl_xor_sync(0xffffffffu, mxB, 1));
            mxB = fmaxf(mxB, __shfl_xor_sync(0xffffffffu, mxB, 2));

            float mAn = fmaxf(mA, mxA), mBn = fmaxf(mB, mxB);
            float fA = __expf(mA - mAn), fB = __expf(mB - mBn);
            mA = mAn; mB = mBn;

            float sA = 0.f, sB = 0.f;
#pragma unroll
            for (int nt = 0; nt < 8; nt++) {
                float p0 = __expf(sa[nt][0] - mA);
                float p1 = __expf(sa[nt][1] - mA);
                float p2 = __expf(sa[nt][2] - mB);
                float p3 = __expf(sa[nt][3] - mB);
                sa[nt][0] = p0; sa[nt][1] = p1; sa[nt][2] = p2; sa[nt][3] = p3;
                sA += p0 + p1; sB += p2 + p3;
            }
            sA += __shfl_xor_sync(0xffffffffu, sA, 1);
            sA += __shfl_xor_sync(0xffffffffu, sA, 2);
            sB += __shfl_xor_sync(0xffffffffu, sB, 1);
            sB += __shfl_xor_sync(0xffffffffu, sB, 2);
            lA = lA * fA + sA;
            lB = lB * fB + sB;
#pragma unroll
            for (int nt = 0; nt < 16; nt++) {
                oacc[nt][0] *= fA; oacc[nt][1] *= fA;
                oacc[nt][2] *= fB; oacc[nt][3] *= fB;
            }

            // ---- O += P V (P 2-term from registers, V single) ----
#pragma unroll
            for (int ks = 0; ks < 4; ks++) {
                uint32_t pah[4], pal[4];
                split2h(sa[2 * ks][0],     sa[2 * ks][1],     pah[0], pal[0]);
                split2h(sa[2 * ks][2],     sa[2 * ks][3],     pah[1], pal[1]);
                split2h(sa[2 * ks + 1][0], sa[2 * ks + 1][1], pah[2], pal[2]);
                split2h(sa[2 * ks + 1][2], sa[2 * ks + 1][3], pah[3], pal[3]);
#pragma unroll
                for (int ntp = 0; ntp < 8; ntp++) {
                    uint32_t vh[4];
                    ldsm4t(vh, sb + KVARR + v_off + ks * (16 * ARSB) + ntp * 32);
                    mma16816h(oacc[2 * ntp],     pah, vh);
                    mma16816h(oacc[2 * ntp],     pal, vh);
                    mma16816h(oacc[2 * ntp + 1], pah, vh + 2);
                    mma16816h(oacc[2 * ntp + 1], pal, vh + 2);
                }
            }
        }
        __syncthreads();
    }

    // ---- epilogue: normalize, split, write g_Oh/g_Ol [m][h*128+d] ----
    float invA = 1.f / lA, invB = 1.f / lB;
    size_t mAr = (size_t)b * 2048 + (size_t)rowA;   // rowA is global t
    size_t mBr = mAr + 8;
    int colbase = h * 128 + 2 * t2g;
#pragma unroll
    for (int nt = 0; nt < 16; nt++) {
        int c = colbase + nt * 8;
        uint32_t hi, lo;
        split2h(oacc[nt][0] * invA, oacc[nt][1] * invA, hi, lo);
        *(uint32_t*)(g_Oh + mAr * 2048 + c) = hi;
        *(uint32_t*)(g_Ol + mAr * 2048 + c) = lo;
        split2h(oacc[nt][2] * invB, oacc[nt][3] * invB, hi, lo);
        *(uint32_t*)(g_Oh + mBr * 2048 + c) = hi;
        *(uint32_t*)(g_Ol + mBr * 2048 + c) = lo;
    }
}

// =====================================================================
// host entry
// =====================================================================
extern "C" void kernel_launch(void* const* d_in, const int* in_sizes, int n_in,
                              void* d_out, int out_size) {
    const float* x  = (const float*)d_in[0];
    // d_in[1] = mask (deterministic causal tril -> ignored)
    const float* qk = (const float*)d_in[2];
    const float* kk = (const float*)d_in[3];
    const float* vk = (const float*)d_in[4];
    const float* ok = (const float*)d_in[5];
    float* out = (float*)d_out;

    cudaFuncSetAttribute(gemm_f16<0>, cudaFuncAttributeMaxDynamicSharedMemorySize, SMEM_GEMM);
    cudaFuncSetAttribute(gemm_f16<1>, cudaFuncAttributeMaxDynamicSharedMemorySize, SMEM_GEMM);
    cudaFuncSetAttribute(attn_mma, cudaFuncAttributeMaxDynamicSharedMemorySize, SMEM_ATTN);

    // split/convert inputs
    cvt_x<<<8192, 256>>>(x);
    cvt_wT<0><<<dim3(64, 64), 256>>>(qk);
    cvt_wT<1><<<dim3(32, 64), 256>>>(kk);
    cvt_wT<2><<<dim3(32, 64), 256>>>(vk);
    cvt_wT<3><<<dim3(64, 64), 256>>>(ok);

    // fused QKV projection (Q,K fp32 for rope; V fp16 direct)
    gemm_f16<0><<<dim3(32, 32), 256, SMEM_GEMM>>>(nullptr);

    // RoPE -> fp16 Q (split) / K (single)
    {
        long long total = ((long long)TB * NH_Q * TT + (long long)TB * NH_KV * TT) * 32;
        int blocks = (int)((total + 255) / 256);
        rope_split<<<blocks, 256>>>();
    }

    // tensor-core flash attention (writes g_Oh/g_Ol fp16 split)
    attn_mma<<<dim3(TT / 128, TB * NH_Q), 256, SMEM_ATTN>>>();

    // output projection
    gemm_f16<1><<<dim3(16, 32), 256, SMEM_GEMM>>>(out);
}

// round 9
// speedup vs baseline: 4.7189x; 1.0833x over previous
#include <cuda_runtime.h>
#include <cuda_fp16.h>
#include <math.h>
#include <stdint.h>

// ---------------- problem constants ----------------
#define TB   2
#define TT   2048
#define TC   2048
#define HD   128
#define NH_Q 16      // R*KVH
#define NH_KV 8

// ---------------- device scratch (no allocs allowed) ----------------
// fp16 operands
__device__ __half g_Xh[(size_t)4096 * 2048];   // x hi  [m, k]
__device__ __half g_Xl[(size_t)4096 * 2048];   // x lo
__device__ __half g_Oh[(size_t)4096 * 2048];   // attn out hi [m, k=h*128+d]
__device__ __half g_Ol[(size_t)4096 * 2048];   // attn out lo
// rope'd Q (split) / K (single) and V (single), head-major [BH][T][D]
__device__ __half g_Qh[(size_t)TB * NH_Q  * TT * HD];
__device__ __half g_Ql[(size_t)TB * NH_Q  * TT * HD];
__device__ __half g_Kh[(size_t)TB * NH_KV * TT * HD];
__device__ __half g_Vh[(size_t)TB * NH_KV * TT * HD];
// weights transposed to K-major [N, K=2048], single fp16
__device__ __half g_Wq[(size_t)2048 * 2048];
__device__ __half g_Wk[(size_t)1024 * 2048];
__device__ __half g_Wv[(size_t)1024 * 2048];
__device__ __half g_Wo[(size_t)2048 * 2048];
// rope sin/cos table [T][64]
__device__ float g_sinT[(size_t)TT * 64];
__device__ float g_cosT[(size_t)TT * 64];

// ---------------- PTX helpers ----------------
__device__ __forceinline__ uint32_t smem_u32(const void* p) {
    uint32_t a;
    asm("{ .reg .u64 t; cvta.to.shared.u64 t, %1; cvt.u32.u64 %0, t; }"
        : "=r"(a) : "l"(p));
    return a;
}
__device__ __forceinline__ void cp16(uint32_t s, const void* g) {
    asm volatile("cp.async.cg.shared.global [%0], [%1], 16;" :: "r"(s), "l"(g));
}
__device__ __forceinline__ void cp_commit() {
    asm volatile("cp.async.commit_group;" ::: "memory");
}
template<int N> __device__ __forceinline__ void cp_wait() {
    asm volatile("cp.async.wait_group %0;" :: "n"(N) : "memory");
}
__device__ __forceinline__ void ldsm4(uint32_t* d, uint32_t addr) {
    asm volatile("ldmatrix.sync.aligned.m8n8.x4.shared.b16 {%0,%1,%2,%3}, [%4];"
                 : "=r"(d[0]), "=r"(d[1]), "=r"(d[2]), "=r"(d[3]) : "r"(addr));
}
__device__ __forceinline__ void ldsm4t(uint32_t* d, uint32_t addr) {
    asm volatile("ldmatrix.sync.aligned.m8n8.x4.trans.shared.b16 {%0,%1,%2,%3}, [%4];"
                 : "=r"(d[0]), "=r"(d[1]), "=r"(d[2]), "=r"(d[3]) : "r"(addr));
}
__device__ __forceinline__ void ldsm2(uint32_t* d, uint32_t addr) {
    asm volatile("ldmatrix.sync.aligned.m8n8.x2.shared.b16 {%0,%1}, [%2];"
                 : "=r"(d[0]), "=r"(d[1]) : "r"(addr));
}
__device__ __forceinline__ void mma16816h(float* c, const uint32_t* a,
                                          const uint32_t* b) {
    asm volatile(
        "mma.sync.aligned.m16n8k16.row.col.f32.f16.f16.f32 "
        "{%0,%1,%2,%3}, {%4,%5,%6,%7}, {%8,%9}, {%0,%1,%2,%3};"
        : "+f"(c[0]), "+f"(c[1]), "+f"(c[2]), "+f"(c[3])
        : "r"(a[0]), "r"(a[1]), "r"(a[2]), "r"(a[3]), "r"(b[0]), "r"(b[1]));
}
__device__ __forceinline__ void split2h(float a, float b, uint32_t& hi, uint32_t& lo) {
    __half2 h = __floats2half2_rn(a, b);
    float ra = a - __half2float(h.x);
    float rb = b - __half2float(h.y);
    __half2 l = __floats2half2_rn(ra, rb);
    hi = *reinterpret_cast<uint32_t*>(&h);
    lo = *reinterpret_cast<uint32_t*>(&l);
}
__device__ __forceinline__ uint32_t pack2h(float a, float b) {
    __half2 h = __floats2half2_rn(a, b);
    return *reinterpret_cast<uint32_t*>(&h);
}
// 50*tanh(x*CS) where CS = rsqrt(128)/50, via exp (accurate ~1e-6 rel)
__device__ __forceinline__ float softcap(float x) {
    const float C2 = 2.0f * 0.08838834764831845f / 50.0f;
    float t = __expf(x * C2);
    return 50.0f * __fdividef(t - 1.0f, t + 1.0f);
}

// ---------------- rope table ----------------
__global__ void rope_tab() {
    int gid = blockIdx.x * 256 + threadIdx.x;   // 0..131071
    int d = gid & 63, t = gid >> 6;
    double ts_d = pow(1.0e6, (double)d * (1.0 / 64.0));
    float arg = __fdiv_rn((float)t, (float)ts_d);
    double da = (double)arg;
    double n  = rint(da * 0.15915494309189535);
    double rr = fma(n, -6.283185307179586, da);
    float rf = (float)rr;
    g_sinT[gid] = sinf(rf);
    g_cosT[gid] = cosf(rf);
}

// ---------------- conversion kernels ----------------
__global__ void cvt_x(const float* __restrict__ x) {
    size_t i = (size_t)blockIdx.x * 256 + threadIdx.x;   // per float4
    float4 v = ((const float4*)x)[i];
    uint32_t h0, l0, h1, l1;
    split2h(v.x, v.y, h0, l0);
    split2h(v.z, v.w, h1, l1);
    ((uint32_t*)g_Xh)[i * 2]     = h0;
    ((uint32_t*)g_Xh)[i * 2 + 1] = h1;
    ((uint32_t*)g_Xl)[i * 2]     = l0;
    ((uint32_t*)g_Xl)[i * 2 + 1] = l1;
}

// W [2048, N] fp32 -> WT [N, 2048] fp16 (single, rounded)
template<int WSEL>
__global__ void cvt_wT(const float* __restrict__ W) {
    __shared__ float tile[32][33];
    const int N = (WSEL == 1 || WSEL == 2) ? 1024 : 2048;
    __half* WT = (WSEL == 0) ? g_Wq : (WSEL == 1) ? g_Wk :
                 (WSEL == 2) ? g_Wv : g_Wo;
    int nb = blockIdx.x * 32, kb = blockIdx.y * 32;
    int tx = threadIdx.x & 31, ty = threadIdx.x >> 5;
#pragma unroll
    for (int r = 0; r < 32; r += 8)
        tile[ty + r][tx] = W[(size_t)(kb + ty + r) * N + nb + tx];
    __syncthreads();
#pragma unroll
    for (int r = 0; r < 32; r += 8) {
        int n = nb + ty + r, k = kb + tx;
        WT[(size_t)n * 2048 + k] = __float2half_rn(tile[tx][ty + r]);
    }
}

// ---------------- mma.sync fp16 2-term GEMM ----------------
// SEL 0: fused QKV projection, N-space 4096 = [Q 2048 | K 1024 | V 1024];
//        Q/K rope applied in-epilogue via smem staging + table.
// SEL 1: output projection, writes d_out fp32.
#define ROWB     80
#define OPB      10240
#define STAGEB   30720
#define NSTG     3
#define SMEM_GEMM (NSTG * STAGEB)

__device__ __forceinline__ void load_stage(uint32_t sb,
        const __half* __restrict__ Ah, const __half* __restrict__ Al,
        const __half* __restrict__ Bp, int bm, int k0, int tid) {
#pragma unroll
    for (int j = 0; j < 2; j++) {
        int idx = tid * 2 + j;
        int r = idx >> 2, c = idx & 3;
        uint32_t so = (uint32_t)r * ROWB + (uint32_t)c * 16u;
        size_t ga = (size_t)(bm + r) * 2048 + k0 + c * 8;
        size_t gb = (size_t)r * 2048 + k0 + c * 8;
        cp16(sb +           so, Ah + ga);
        cp16(sb + OPB     + so, Al + ga);
        cp16(sb + 2 * OPB + so, Bp + gb);
    }
}

template<int SEL>
__global__ void __launch_bounds__(256) gemm_f16(float* __restrict__ outp) {
    extern __shared__ __align__(128) char dsm[];
    const uint32_t smem0 = smem_u32(dsm);

    const int tid = threadIdx.x;
    const int lid = tid & 31;
    const int wid = tid >> 5;
    const int wm = wid >> 2;
    const int wn = wid & 3;
    const int bn = blockIdx.x * 128;
    const int bm = blockIdx.y * 128;

    const __half *Ah, *Al, *Bp;
    if (SEL == 1) {
        Ah = g_Oh; Al = g_Ol;
        Bp = g_Wo + (size_t)bn * 2048;
    } else {
        Ah = g_Xh; Al = g_Xl;
        if (bn < 2048)      Bp = g_Wq + (size_t)bn * 2048;
        else if (bn < 3072) Bp = g_Wk + (size_t)(bn - 2048) * 2048;
        else                Bp = g_Wv + (size_t)(bn - 3072) * 2048;
    }

    const int r8 = lid & 7, gq = lid >> 3;
    const uint32_t aoff = (uint32_t)((gq & 1) * 8 + r8) * ROWB +
                          (uint32_t)(gq >> 1) * 16u + (uint32_t)wm * 64u * ROWB;
    const int lb = lid & 15;
    const uint32_t boff = (uint32_t)(lb & 7) * ROWB +
                          (uint32_t)(lb >> 3) * 16u + (uint32_t)wn * 32u * ROWB;

    float acc[4][4][4];
#pragma unroll
    for (int i = 0; i < 4; i++)
#pragma unroll
        for (int j = 0; j < 4; j++)
#pragma unroll
            for (int k = 0; k < 4; k++) acc[i][j][k] = 0.f;

    load_stage(smem0, Ah, Al, Bp, bm, 0, tid);
    cp_commit();
    load_stage(smem0 + STAGEB, Ah, Al, Bp, bm, 32, tid);
    cp_commit();

    const int NI = 64;
    int sidx = 0;
    for (int i = 0; i < NI; i++) {
        if (i + 2 < NI) {
            int ns = sidx + 2; if (ns >= NSTG) ns -= NSTG;
            load_stage(smem0 + ns * STAGEB, Ah, Al, Bp, bm, (i + 2) * 32, tid);
            cp_commit();
            cp_wait<2>();
        } else if (i + 1 < NI) {
            cp_wait<1>();
        } else {
            cp_wait<0>();
        }
        __syncthreads();

        const uint32_t sb = smem0 + sidx * STAGEB;
#pragma unroll
        for (int kk = 0; kk < 2; kk++) {
            uint32_t ah[4][4], al[4][4], bf[4][2];
#pragma unroll
            for (int mt = 0; mt < 4; mt++) {
                uint32_t base = sb + aoff + mt * (16 * ROWB) + kk * 32;
                ldsm4(ah[mt], base);
                ldsm4(al[mt], base + OPB);
            }
#pragma unroll
            for (int nt = 0; nt < 4; nt++)
                ldsm2(bf[nt], sb + 2 * OPB + boff + nt * (8 * ROWB) + kk * 32);
#pragma unroll
            for (int mt = 0; mt < 4; mt++)
#pragma unroll
                for (int nt = 0; nt < 4; nt++) {
                    mma16816h(acc[mt][nt], ah[mt], bf[nt]);
                    mma16816h(acc[mt][nt], al[mt], bf[nt]);
                }
        }
        __syncthreads();
        if (++sidx >= NSTG) sidx = 0;
    }

    const int t4 = lid >> 2, t2 = (lid & 3) << 1;

    if (SEL == 0 && bn < 3072) {
        // ---- Q/K: stage fp32 tile in smem, apply rope, emit fp16 ----
        float* sQ = reinterpret_cast<float*>(dsm);   // [128][130]
#pragma unroll
        for (int mt = 0; mt < 4; mt++) {
            int r0 = wm * 64 + mt * 16 + t4;
#pragma unroll
            for (int half = 0; half < 2; half++) {
                int r = r0 + half * 8;
#pragma unroll
                for (int nt = 0; nt < 4; nt++) {
                    int col = wn * 32 + nt * 8 + t2;
                    sQ[r * 130 + col]     = acc[mt][nt][half * 2];
                    sQ[r * 130 + col + 1] = acc[mt][nt][half * 2 + 1];
                }
            }
        }
        __syncthreads();

        const bool isQ = (bn < 2048);
        const int head = isQ ? (bn >> 7) : ((bn - 2048) >> 7);
#pragma unroll
        for (int pass = 0; pass < 16; pass++) {
            int u = tid + pass * 256;          // 0..4095
            int r = u >> 5;                    // 0..127
            int d2 = (u & 31) * 2;             // 0,2,..,62
            int m = bm + r;
            int b = m >> 11, t = m & 2047;
            float u1a = sQ[r * 130 + d2],      u1b = sQ[r * 130 + d2 + 1];
            float u2a = sQ[r * 130 + d2 + 64], u2b = sQ[r * 130 + d2 + 65];
            float ca = g_cosT[t * 64 + d2],     sa_ = g_sinT[t * 64 + d2];
            float cb = g_cosT[t * 64 + d2 + 1], sb_ = g_sinT[t * 64 + d2 + 1];
            float y1a = u1a * ca - u2a * sa_, y1b = u1b * cb - u2b * sb_;
            float y2a = u2a * ca + u1a * sa_, y2b = u2b * cb + u1b * sb_;
            if (isQ) {
                size_t o = (((size_t)b * NH_Q + head) * TT + t) * HD + d2;
                uint32_t hi, lo;
                split2h(y1a, y1b, hi, lo);
                *(uint32_t*)(g_Qh + o) = hi;  *(uint32_t*)(g_Ql + o) = lo;
                split2h(y2a, y2b, hi, lo);
                *(uint32_t*)(g_Qh + o + 64) = hi;  *(uint32_t*)(g_Ql + o + 64) = lo;
            } else {
                size_t o = (((size_t)b * NH_KV + head) * TT + t) * HD + d2;
                *(uint32_t*)(g_Kh + o)      = pack2h(y1a, y1b);
                *(uint32_t*)(g_Kh + o + 64) = pack2h(y2a, y2b);
            }
        }
        return;
    }

    // ---- V (fp16 single) or out-proj (fp32) ----
#pragma unroll
    for (int mt = 0; mt < 4; mt++) {
        int m0 = bm + wm * 64 + mt * 16 + t4;
#pragma unroll
        for (int half = 0; half < 2; half++) {
            int m = m0 + half * 8;
            int b = m >> 11, t = m & 2047;
            if (SEL == 1) {
                float* dst = outp + (size_t)m * 2048 + bn;
#pragma unroll
                for (int nt = 0; nt < 4; nt++) {
                    int col = wn * 32 + nt * 8 + t2;
                    *(float2*)(dst + col) =
                        make_float2(acc[mt][nt][half * 2], acc[mt][nt][half * 2 + 1]);
                }
            } else {
                int head = (bn - 3072) >> 7;
                size_t ro = (((size_t)b * NH_KV + head) * TT + t) * HD;
#pragma unroll
                for (int nt = 0; nt < 4; nt++) {
                    int col = wn * 32 + nt * 8 + t2;
                    *(uint32_t*)(g_Vh + ro + col) =
                        pack2h(acc[mt][nt][half * 2], acc[mt][nt][half * 2 + 1]);
                }
            }
        }
    }
}

// =====================================================================
// Flash attention: BM=64, BN=64, 4 warps / 128 threads, 2 CTAs/SM.
// Q split fp16 (2-term), K/V single fp16, P split fp16.  fp32 accum.
// =====================================================================
#define ARSB  272
#define QSZ   (64 * ARSB)        // 17408 per Q array
#define KVARR (64 * ARSB)        // 17408 per operand array
#define KVSTG (2 * KVARR)        // 34816 per stage (Kh, Vh)
#define SMEM_ATTN (2 * QSZ + 2 * KVSTG)   // 104448

__device__ __forceinline__ void load_kv(uint32_t sb,
        const __half* __restrict__ Khp, const __half* __restrict__ Vhp,
        int kv0, int tid) {
#pragma unroll
    for (int tpass = 0; tpass < 8; tpass++) {
        int idx = tid + tpass * 128;        // 0..1023
        int r = idx >> 4, cc = idx & 15;
        uint32_t so = (uint32_t)r * ARSB + (uint32_t)cc * 16u;
        size_t go = (size_t)(kv0 + r) * HD + cc * 8;
        cp16(sb +         so, Khp + go);
        cp16(sb + KVARR + so, Vhp + go);
    }
}

__global__ void __launch_bounds__(128) attn_mma() {
    extern __shared__ __align__(128) char asmem[];
    const uint32_t s0  = smem_u32(asmem);
    const uint32_t qhS = s0;
    const uint32_t qlS = s0 + QSZ;
    const uint32_t kvb = s0 + 2 * QSZ;

    const int i0 = gridDim.x - 1 - blockIdx.x;    // heavy blocks first
    const int bh = blockIdx.y;                    // b*16 + h
    const int b  = bh >> 4;
    const int h  = bh & 15;
    const int hkv = h & 7;

    const __half* Qhp = g_Qh + (size_t)bh * TT * HD;
    const __half* Qlp = g_Ql + (size_t)bh * TT * HD;
    const size_t kvo = ((size_t)b * NH_KV + hkv) * TT * HD;
    const __half* Khp = g_Kh + kvo;
    const __half* Vhp = g_Vh + kvo;

    const int tid = threadIdx.x, lid = tid & 31, wid = tid >> 5;
    const int t4 = lid >> 2, t2g = lid & 3;
    const int warpRow = wid * 16;

    const uint32_t a_off = (uint32_t)(warpRow + (lid & 7) + ((lid >> 3) & 1) * 8) * ARSB +
                           (uint32_t)(lid >> 4) * 16u;
    const uint32_t bk_off = (uint32_t)(lid & 7) * ARSB + (uint32_t)(lid >> 3) * 16u;
    const uint32_t v_off  = (uint32_t)((lid & 7) + ((lid >> 3) & 1) * 8) * ARSB +
                            (uint32_t)(lid >> 4) * 16u;

    // load Q tile (hi+lo): 64 rows x 16 chunks
    {
        int r0q = i0 * 64;
#pragma unroll
        for (int tp = 0; tp < 8; tp++) {
            int idx = tid + tp * 128;       // 0..1023
            int r = idx >> 4, cc = idx & 15;
            uint32_t so = (uint32_t)r * ARSB + (uint32_t)cc * 16u;
            size_t go = (size_t)(r0q + r) * HD + cc * 8;
            cp16(qhS + so, Qhp + go);
            cp16(qlS + so, Qlp + go);
        }
    }
    load_kv(kvb, Khp, Vhp, 0, tid);
    cp_commit();

    float oacc[16][4];
#pragma unroll
    for (int i = 0; i < 16; i++)
#pragma unroll
        for (int j = 0; j < 4; j++) oacc[i][j] = 0.f;
    float mA = -1e30f, mB = -1e30f, lA = 0.f, lB = 0.f;

    const int rowA = i0 * 64 + warpRow + t4;
    const int rowB = rowA + 8;
    const int nj = i0 + 1;

    for (int j = 0; j < nj; j++) {
        if (j + 1 < nj) {
            load_kv(kvb + ((j + 1) & 1) * KVSTG, Khp, Vhp, (j + 1) * 64, tid);
            cp_commit();
            cp_wait<1>();
        } else {
            cp_wait<0>();
        }
        __syncthreads();

        const uint32_t sb = kvb + (j & 1) * KVSTG;

        // ---- S = Q K^T (Q 2-term, K single) ----
        float sa[8][4];
#pragma unroll
        for (int nt = 0; nt < 8; nt++)
#pragma unroll
            for (int q = 0; q < 4; q++) sa[nt][q] = 0.f;

#pragma unroll
        for (int kp = 0; kp < 4; kp++) {
            uint32_t q0h[4], q1h[4], q0l[4], q1l[4];
            ldsm4(q0h, qhS + a_off + kp * 64);
            ldsm4(q1h, qhS + a_off + kp * 64 + 32);
            ldsm4(q0l, qlS + a_off + kp * 64);
            ldsm4(q1l, qlS + a_off + kp * 64 + 32);
#pragma unroll
            for (int nt = 0; nt < 8; nt++) {
                uint32_t kh[4];
                ldsm4(kh, sb + bk_off + nt * (8 * ARSB) + kp * 64);
                mma16816h(sa[nt], q0h, kh);
                mma16816h(sa[nt], q0l, kh);
                mma16816h(sa[nt], q1h, kh + 2);
                mma16816h(sa[nt], q1l, kh + 2);
            }
        }

        // ---- softcap + mask + online softmax ----
        float mxA = -1e30f, mxB = -1e30f;
#pragma unroll
        for (int nt = 0; nt < 8; nt++) {
            int c0 = j * 64 + nt * 8 + 2 * t2g;
            float v0 = softcap(sa[nt][0]);
            float v1 = softcap(sa[nt][1]);
            float v2 = softcap(sa[nt][2]);
            float v3 = softcap(sa[nt][3]);
            if (c0     > rowA) v0 = -1e30f;
            if (c0 + 1 > rowA) v1 = -1e30f;
            if (c0     > rowB) v2 = -1e30f;
            if (c0 + 1 > rowB) v3 = -1e30f;
            sa[nt][0] = v0; sa[nt][1] = v1; sa[nt][2] = v2; sa[nt][3] = v3;
            mxA = fmaxf(mxA, fmaxf(v0, v1));
            mxB = fmaxf(mxB, fmaxf(v2, v3));
        }
        mxA = fmaxf(mxA, __shfl_xor_sync(0xffffffffu, mxA, 1));
        mxA = fmaxf(mxA, __shfl_xor_sync(0xffffffffu, mxA, 2));
        mxB = fmaxf(mxB, __shfl_xor_sync(0xffffffffu, mxB, 1));
        mxB = fmaxf(mxB, __shfl_xor_sync(0xffffffffu, mxB, 2));

        float mAn = fmaxf(mA, mxA), mBn = fmaxf(mB, mxB);
        float fA = __expf(mA - mAn), fB = __expf(mB - mBn);
        mA = mAn; mB = mBn;

        float sA = 0.f, sB = 0.f;
#pragma unroll
        for (int nt = 0; nt < 8; nt++) {
            float p0 = __expf(sa[nt][0] - mA);
            float p1 = __expf(sa[nt][1] - mA);
            float p2 = __expf(sa[nt][2] - mB);
            float p3 = __expf(sa[nt][3] - mB);
            sa[nt][0] = p0; sa[nt][1] = p1; sa[nt][2] = p2; sa[nt][3] = p3;
            sA += p0 + p1; sB += p2 + p3;
        }
        sA += __shfl_xor_sync(0xffffffffu, sA, 1);
        sA += __shfl_xor_sync(0xffffffffu, sA, 2);
        sB += __shfl_xor_sync(0xffffffffu, sB, 1);
        sB += __shfl_xor_sync(0xffffffffu, sB, 2);
        lA = lA * fA + sA;
        lB = lB * fB + sB;
#pragma unroll
        for (int nt = 0; nt < 16; nt++) {
            oacc[nt][0] *= fA; oacc[nt][1] *= fA;
            oacc[nt][2] *= fB; oacc[nt][3] *= fB;
        }

        // ---- O += P V (P 2-term from registers, V single) ----
#pragma unroll
        for (int ks = 0; ks < 4; ks++) {
            uint32_t pah[4], pal[4];
            split2h(sa[2 * ks][0],     sa[2 * ks][1],     pah[0], pal[0]);
            split2h(sa[2 * ks][2],     sa[2 * ks][3],     pah[1], pal[1]);
            split2h(sa[2 * ks + 1][0], sa[2 * ks + 1][1], pah[2], pal[2]);
            split2h(sa[2 * ks + 1][2], sa[2 * ks + 1][3], pah[3], pal[3]);
#pragma unroll
            for (int ntp = 0; ntp < 8; ntp++) {
                uint32_t vh[4];
                ldsm4t(vh, sb + KVARR + v_off + ks * (16 * ARSB) + ntp * 32);
                mma16816h(oacc[2 * ntp],     pah, vh);
                mma16816h(oacc[2 * ntp],     pal, vh);
                mma16816h(oacc[2 * ntp + 1], pah, vh + 2);
                mma16816h(oacc[2 * ntp + 1], pal, vh + 2);
            }
        }
        __syncthreads();
    }

    // ---- epilogue: normalize, split, write g_Oh/g_Ol [m][h*128+d] ----
    float invA = 1.f / lA, invB = 1.f / lB;
    size_t mAr = (size_t)b * 2048 + (size_t)rowA;   // rowA is global t
    size_t mBr = mAr + 8;
    int colbase = h * 128 + 2 * t2g;
#pragma unroll
    for (int nt = 0; nt < 16; nt++) {
        int c = colbase + nt * 8;
        uint32_t hi, lo;
        split2h(oacc[nt][0] * invA, oacc[nt][1] * invA, hi, lo);
        *(uint32_t*)(g_Oh + mAr * 2048 + c) = hi;
        *(uint32_t*)(g_Ol + mAr * 2048 + c) = lo;
        split2h(oacc[nt][2] * invB, oacc[nt][3] * invB, hi, lo);
        *(uint32_t*)(g_Oh + mBr * 2048 + c) = hi;
        *(uint32_t*)(g_Ol + mBr * 2048 + c) = lo;
    }
}

// =====================================================================
// host entry
// =====================================================================
extern "C" void kernel_launch(void* const* d_in, const int* in_sizes, int n_in,
                              void* d_out, int out_size) {
    const float* x  = (const float*)d_in[0];
    // d_in[1] = mask (deterministic causal tril -> ignored)
    const float* qk = (const float*)d_in[2];
    const float* kk = (const float*)d_in[3];
    const float* vk = (const float*)d_in[4];
    const float* ok = (const float*)d_in[5];
    float* out = (float*)d_out;

    cudaFuncSetAttribute(gemm_f16<0>, cudaFuncAttributeMaxDynamicSharedMemorySize, SMEM_GEMM);
    cudaFuncSetAttribute(gemm_f16<1>, cudaFuncAttributeMaxDynamicSharedMemorySize, SMEM_GEMM);
    cudaFuncSetAttribute(attn_mma, cudaFuncAttributeMaxDynamicSharedMemorySize, SMEM_ATTN);

    // rope table + input conversion
    rope_tab<<<512, 256>>>();
    cvt_x<<<8192, 256>>>(x);
    cvt_wT<0><<<dim3(64, 64), 256>>>(qk);
    cvt_wT<1><<<dim3(32, 64), 256>>>(kk);
    cvt_wT<2><<<dim3(32, 64), 256>>>(vk);
    cvt_wT<3><<<dim3(64, 64), 256>>>(ok);

    // fused QKV projection + rope epilogue
    gemm_f16<0><<<dim3(32, 32), 256, SMEM_GEMM>>>(nullptr);

    // tensor-core flash attention (writes g_Oh/g_Ol fp16 split)
    attn_mma<<<dim3(TT / 64, TB * NH_Q), 128, SMEM_ATTN>>>();

    // output projection
    gemm_f16<1><<<dim3(16, 32), 256, SMEM_GEMM>>>(out);
}

// round 10
// speedup vs baseline: 6.3808x; 1.3522x over previous
#include <cuda_runtime.h>
#include <cuda_fp16.h>
#include <math.h>
#include <stdint.h>

// ---------------- problem constants ----------------
#define TB   2
#define TT   2048
#define TC   2048
#define HD   128
#define NH_Q 16      // R*KVH
#define NH_KV 8

// ---------------- device scratch (no allocs allowed) ----------------
__device__ __half g_Xh[(size_t)4096 * 2048];   // x fp16 single [m, k]
__device__ __half g_Oh[(size_t)4096 * 2048];   // attn out fp16 single [m, h*128+d]
// rope'd Q (split) / K (single) and V (single), head-major [BH][T][D]
__device__ __half g_Qh[(size_t)TB * NH_Q  * TT * HD];
__device__ __half g_Ql[(size_t)TB * NH_Q  * TT * HD];
__device__ __half g_Kh[(size_t)TB * NH_KV * TT * HD];
__device__ __half g_Vh[(size_t)TB * NH_KV * TT * HD];
// weights transposed to K-major [N, K=2048], single fp16
__device__ __half g_Wq[(size_t)2048 * 2048];
__device__ __half g_Wk[(size_t)1024 * 2048];
__device__ __half g_Wv[(size_t)1024 * 2048];
__device__ __half g_Wo[(size_t)2048 * 2048];
// rope sin/cos table [T][64]
__device__ float g_sinT[(size_t)TT * 64];
__device__ float g_cosT[(size_t)TT * 64];

// ---------------- PTX helpers ----------------
__device__ __forceinline__ uint32_t smem_u32(const void* p) {
    uint32_t a;
    asm("{ .reg .u64 t; cvta.to.shared.u64 t, %1; cvt.u32.u64 %0, t; }"
        : "=r"(a) : "l"(p));
    return a;
}
__device__ __forceinline__ void cp16(uint32_t s, const void* g) {
    asm volatile("cp.async.cg.shared.global [%0], [%1], 16;" :: "r"(s), "l"(g));
}
__device__ __forceinline__ void cp_commit() {
    asm volatile("cp.async.commit_group;" ::: "memory");
}
template<int N> __device__ __forceinline__ void cp_wait() {
    asm volatile("cp.async.wait_group %0;" :: "n"(N) : "memory");
}
__device__ __forceinline__ void ldsm4(uint32_t* d, uint32_t addr) {
    asm volatile("ldmatrix.sync.aligned.m8n8.x4.shared.b16 {%0,%1,%2,%3}, [%4];"
                 : "=r"(d[0]), "=r"(d[1]), "=r"(d[2]), "=r"(d[3]) : "r"(addr));
}
__device__ __forceinline__ void ldsm4t(uint32_t* d, uint32_t addr) {
    asm volatile("ldmatrix.sync.aligned.m8n8.x4.trans.shared.b16 {%0,%1,%2,%3}, [%4];"
                 : "=r"(d[0]), "=r"(d[1]), "=r"(d[2]), "=r"(d[3]) : "r"(addr));
}
__device__ __forceinline__ void ldsm2(uint32_t* d, uint32_t addr) {
    asm volatile("ldmatrix.sync.aligned.m8n8.x2.shared.b16 {%0,%1}, [%2];"
                 : "=r"(d[0]), "=r"(d[1]) : "r"(addr));
}
__device__ __forceinline__ void mma16816h(float* c, const uint32_t* a,
                                          const uint32_t* b) {
    asm volatile(
        "mma.sync.aligned.m16n8k16.row.col.f32.f16.f16.f32 "
        "{%0,%1,%2,%3}, {%4,%5,%6,%7}, {%8,%9}, {%0,%1,%2,%3};"
        : "+f"(c[0]), "+f"(c[1]), "+f"(c[2]), "+f"(c[3])
        : "r"(a[0]), "r"(a[1]), "r"(a[2]), "r"(a[3]), "r"(b[0]), "r"(b[1]));
}
__device__ __forceinline__ void split2h(float a, float b, uint32_t& hi, uint32_t& lo) {
    __half2 h = __floats2half2_rn(a, b);
    float ra = a - __half2float(h.x);
    float rb = b - __half2float(h.y);
    __half2 l = __floats2half2_rn(ra, rb);
    hi = *reinterpret_cast<uint32_t*>(&h);
    lo = *reinterpret_cast<uint32_t*>(&l);
}
__device__ __forceinline__ uint32_t pack2h(float a, float b) {
    __half2 h = __floats2half2_rn(a, b);
    return *reinterpret_cast<uint32_t*>(&h);
}
// 50*tanh(x*CS) where CS = rsqrt(128)/50, via exp (accurate ~1e-6 rel)
__device__ __forceinline__ float softcap(float x) {
    const float C2 = 2.0f * 0.08838834764831845f / 50.0f;
    float t = __expf(x * C2);
    return 50.0f * __fdividef(t - 1.0f, t + 1.0f);
}

// ---------------- rope table ----------------
__global__ void rope_tab() {
    int gid = blockIdx.x * 256 + threadIdx.x;   // 0..131071
    int d = gid & 63, t = gid >> 6;
    double ts_d = pow(1.0e6, (double)d * (1.0 / 64.0));
    float arg = __fdiv_rn((float)t, (float)ts_d);
    double da = (double)arg;
    double n  = rint(da * 0.15915494309189535);
    double rr = fma(n, -6.283185307179586, da);
    float rf = (float)rr;
    g_sinT[gid] = sinf(rf);
    g_cosT[gid] = cosf(rf);
}

// ---------------- conversion kernels ----------------
__global__ void cvt_x(const float* __restrict__ x) {
    size_t i = (size_t)blockIdx.x * 256 + threadIdx.x;   // per float4
    float4 v = ((const float4*)x)[i];
    ((uint32_t*)g_Xh)[i * 2]     = pack2h(v.x, v.y);
    ((uint32_t*)g_Xh)[i * 2 + 1] = pack2h(v.z, v.w);
}

// all 4 weight transposes in one launch
__global__ void cvt_w_all(const float* __restrict__ q, const float* __restrict__ k,
                          const float* __restrict__ v, const float* __restrict__ o) {
    __shared__ float tile[32][33];
    int bx = blockIdx.x;
    const float* W; __half* WT; int N, nb;
    if (bx < 64)       { W = q; WT = g_Wq; N = 2048; nb = bx * 32; }
    else if (bx < 96)  { W = k; WT = g_Wk; N = 1024; nb = (bx - 64) * 32; }
    else if (bx < 128) { W = v; WT = g_Wv; N = 1024; nb = (bx - 96) * 32; }
    else               { W = o; WT = g_Wo; N = 2048; nb = (bx - 128) * 32; }
    int kb = blockIdx.y * 32;
    int tx = threadIdx.x & 31, ty = threadIdx.x >> 5;
#pragma unroll
    for (int r = 0; r < 32; r += 8)
        tile[ty + r][tx] = W[(size_t)(kb + ty + r) * N + nb + tx];
    __syncthreads();
#pragma unroll
    for (int r = 0; r < 32; r += 8) {
        int n = nb + ty + r, kk = kb + tx;
        WT[(size_t)n * 2048 + kk] = __float2half_rn(tile[tx][ty + r]);
    }
}

// ---------------- mma.sync fp16 single-term GEMM ----------------
// SEL 0: fused QKV projection, N-space 4096 = [Q 2048 | K 1024 | V 1024];
//        Q/K rope applied in-epilogue via smem staging + table.
// SEL 1: output projection, writes d_out fp32.
#define ROWB     80
#define OPB      10240
#define STAGEB   20480
#define NSTG     3
#define SMEM_GEMM0 66560            // max(3*20480, 128*130*4 rope staging)
#define SMEM_GEMM1 (NSTG * STAGEB)  // 61440

__device__ __forceinline__ void load_stage(uint32_t sb,
        const __half* __restrict__ Ah, const __half* __restrict__ Bp,
        int bm, int k0, int tid) {
#pragma unroll
    for (int j = 0; j < 2; j++) {
        int idx = tid * 2 + j;
        int r = idx >> 2, c = idx & 3;
        uint32_t so = (uint32_t)r * ROWB + (uint32_t)c * 16u;
        cp16(sb +       so, Ah + (size_t)(bm + r) * 2048 + k0 + c * 8);
        cp16(sb + OPB + so, Bp + (size_t)r * 2048 + k0 + c * 8);
    }
}

template<int SEL>
__global__ void __launch_bounds__(256, 2) gemm_f16(float* __restrict__ outp) {
    extern __shared__ __align__(128) char dsm[];
    const uint32_t smem0 = smem_u32(dsm);

    const int tid = threadIdx.x;
    const int lid = tid & 31;
    const int wid = tid >> 5;
    const int wm = wid >> 2;
    const int wn = wid & 3;
    const int bn = blockIdx.x * 128;
    const int bm = blockIdx.y * 128;

    const __half *Ah, *Bp;
    if (SEL == 1) {
        Ah = g_Oh;
        Bp = g_Wo + (size_t)bn * 2048;
    } else {
        Ah = g_Xh;
        if (bn < 2048)      Bp = g_Wq + (size_t)bn * 2048;
        else if (bn < 3072) Bp = g_Wk + (size_t)(bn - 2048) * 2048;
        else                Bp = g_Wv + (size_t)(bn - 3072) * 2048;
    }

    const int r8 = lid & 7, gq = lid >> 3;
    const uint32_t aoff = (uint32_t)((gq & 1) * 8 + r8) * ROWB +
                          (uint32_t)(gq >> 1) * 16u + (uint32_t)wm * 64u * ROWB;
    const int lb = lid & 15;
    const uint32_t boff = (uint32_t)(lb & 7) * ROWB +
                          (uint32_t)(lb >> 3) * 16u + (uint32_t)wn * 32u * ROWB;

    float acc[4][4][4];
#pragma unroll
    for (int i = 0; i < 4; i++)
#pragma unroll
        for (int j = 0; j < 4; j++)
#pragma unroll
            for (int k = 0; k < 4; k++) acc[i][j][k] = 0.f;

    load_stage(smem0, Ah, Bp, bm, 0, tid);
    cp_commit();
    load_stage(smem0 + STAGEB, Ah, Bp, bm, 32, tid);
    cp_commit();

    const int NI = 64;
    int sidx = 0;
    for (int i = 0; i < NI; i++) {
        if (i + 2 < NI) {
            int ns = sidx + 2; if (ns >= NSTG) ns -= NSTG;
            load_stage(smem0 + ns * STAGEB, Ah, Bp, bm, (i + 2) * 32, tid);
            cp_commit();
            cp_wait<2>();
        } else if (i + 1 < NI) {
            cp_wait<1>();
        } else {
            cp_wait<0>();
        }
        __syncthreads();

        const uint32_t sb = smem0 + sidx * STAGEB;
#pragma unroll
        for (int kk = 0; kk < 2; kk++) {
            uint32_t ah[4][4], bf[4][2];
#pragma unroll
            for (int mt = 0; mt < 4; mt++)
                ldsm4(ah[mt], sb + aoff + mt * (16 * ROWB) + kk * 32);
#pragma unroll
            for (int nt = 0; nt < 4; nt++)
                ldsm2(bf[nt], sb + OPB + boff + nt * (8 * ROWB) + kk * 32);
#pragma unroll
            for (int mt = 0; mt < 4; mt++)
#pragma unroll
                for (int nt = 0; nt < 4; nt++)
                    mma16816h(acc[mt][nt], ah[mt], bf[nt]);
        }
        __syncthreads();
        if (++sidx >= NSTG) sidx = 0;
    }

    const int t4 = lid >> 2, t2 = (lid & 3) << 1;

    if (SEL == 0 && bn < 3072) {
        // ---- Q/K: stage fp32 tile in smem, apply rope, emit fp16 ----
        float* sQ = reinterpret_cast<float*>(dsm);   // [128][130]
#pragma unroll
        for (int mt = 0; mt < 4; mt++) {
            int r0 = wm * 64 + mt * 16 + t4;
#pragma unroll
            for (int half = 0; half < 2; half++) {
                int r = r0 + half * 8;
#pragma unroll
                for (int nt = 0; nt < 4; nt++) {
                    int col = wn * 32 + nt * 8 + t2;
                    sQ[r * 130 + col]     = acc[mt][nt][half * 2];
                    sQ[r * 130 + col + 1] = acc[mt][nt][half * 2 + 1];
                }
            }
        }
        __syncthreads();

        const bool isQ = (bn < 2048);
        const int head = isQ ? (bn >> 7) : ((bn - 2048) >> 7);
#pragma unroll
        for (int pass = 0; pass < 16; pass++) {
            int u = tid + pass * 256;          // 0..4095
            int r = u >> 5;                    // 0..127
            int d2 = (u & 31) * 2;             // 0,2,..,62
            int m = bm + r;
            int b = m >> 11, t = m & 2047;
            float u1a = sQ[r * 130 + d2],      u1b = sQ[r * 130 + d2 + 1];
            float u2a = sQ[r * 130 + d2 + 64], u2b = sQ[r * 130 + d2 + 65];
            float ca = g_cosT[t * 64 + d2],     sa_ = g_sinT[t * 64 + d2];
            float cb = g_cosT[t * 64 + d2 + 1], sb_ = g_sinT[t * 64 + d2 + 1];
            float y1a = u1a * ca - u2a * sa_, y1b = u1b * cb - u2b * sb_;
            float y2a = u2a * ca + u1a * sa_, y2b = u2b * cb + u1b * sb_;
            if (isQ) {
                size_t o = (((size_t)b * NH_Q + head) * TT + t) * HD + d2;
                uint32_t hi, lo;
                split2h(y1a, y1b, hi, lo);
                *(uint32_t*)(g_Qh + o) = hi;  *(uint32_t*)(g_Ql + o) = lo;
                split2h(y2a, y2b, hi, lo);
                *(uint32_t*)(g_Qh + o + 64) = hi;  *(uint32_t*)(g_Ql + o + 64) = lo;
            } else {
                size_t o = (((size_t)b * NH_KV + head) * TT + t) * HD + d2;
                *(uint32_t*)(g_Kh + o)      = pack2h(y1a, y1b);
                *(uint32_t*)(g_Kh + o + 64) = pack2h(y2a, y2b);
            }
        }
        return;
    }

    // ---- V (fp16 single) or out-proj (fp32) ----
#pragma unroll
    for (int mt = 0; mt < 4; mt++) {
        int m0 = bm + wm * 64 + mt * 16 + t4;
#pragma unroll
        for (int half = 0; half < 2; half++) {
            int m = m0 + half * 8;
            int b = m >> 11, t = m & 2047;
            if (SEL == 1) {
                float* dst = outp + (size_t)m * 2048 + bn;
#pragma unroll
                for (int nt = 0; nt < 4; nt++) {
                    int col = wn * 32 + nt * 8 + t2;
                    *(float2*)(dst + col) =
                        make_float2(acc[mt][nt][half * 2], acc[mt][nt][half * 2 + 1]);
                }
            } else {
                int head = (bn - 3072) >> 7;
                size_t ro = (((size_t)b * NH_KV + head) * TT + t) * HD;
#pragma unroll
                for (int nt = 0; nt < 4; nt++) {
                    int col = wn * 32 + nt * 8 + t2;
                    *(uint32_t*)(g_Vh + ro + col) =
                        pack2h(acc[mt][nt][half * 2], acc[mt][nt][half * 2 + 1]);
                }
            }
        }
    }
}

// =====================================================================
// Flash attention: BM=64, BN=64, 4 warps / 128 threads, 2 CTAs/SM.
// Q split fp16 (2-term), K/V single fp16, P split fp16.  fp32 accum.
// =====================================================================
#define ARSB  272
#define QSZ   (64 * ARSB)        // 17408 per Q array
#define KVARR (64 * ARSB)        // 17408 per operand array
#define KVSTG (2 * KVARR)        // 34816 per stage (Kh, Vh)
#define SMEM_ATTN (2 * QSZ + 2 * KVSTG)   // 104448

__device__ __forceinline__ void load_kv(uint32_t sb,
        const __half* __restrict__ Khp, const __half* __restrict__ Vhp,
        int kv0, int tid) {
#pragma unroll
    for (int tpass = 0; tpass < 8; tpass++) {
        int idx = tid + tpass * 128;        // 0..1023
        int r = idx >> 4, cc = idx & 15;
        uint32_t so = (uint32_t)r * ARSB + (uint32_t)cc * 16u;
        size_t go = (size_t)(kv0 + r) * HD + cc * 8;
        cp16(sb +         so, Khp + go);
        cp16(sb + KVARR + so, Vhp + go);
    }
}

__global__ void __launch_bounds__(128) attn_mma() {
    extern __shared__ __align__(128) char asmem[];
    const uint32_t s0  = smem_u32(asmem);
    const uint32_t qhS = s0;
    const uint32_t qlS = s0 + QSZ;
    const uint32_t kvb = s0 + 2 * QSZ;

    const int i0 = gridDim.x - 1 - blockIdx.x;    // heavy blocks first
    const int bh = blockIdx.y;                    // b*16 + h
    const int b  = bh >> 4;
    const int h  = bh & 15;
    const int hkv = h & 7;

    const __half* Qhp = g_Qh + (size_t)bh * TT * HD;
    const __half* Qlp = g_Ql + (size_t)bh * TT * HD;
    const size_t kvo = ((size_t)b * NH_KV + hkv) * TT * HD;
    const __half* Khp = g_Kh + kvo;
    const __half* Vhp = g_Vh + kvo;

    const int tid = threadIdx.x, lid = tid & 31, wid = tid >> 5;
    const int t4 = lid >> 2, t2g = lid & 3;
    const int warpRow = wid * 16;

    const uint32_t a_off = (uint32_t)(warpRow + (lid & 7) + ((lid >> 3) & 1) * 8) * ARSB +
                           (uint32_t)(lid >> 4) * 16u;
    const uint32_t bk_off = (uint32_t)(lid & 7) * ARSB + (uint32_t)(lid >> 3) * 16u;
    const uint32_t v_off  = (uint32_t)((lid & 7) + ((lid >> 3) & 1) * 8) * ARSB +
                            (uint32_t)(lid >> 4) * 16u;

    // load Q tile (hi+lo): 64 rows x 16 chunks
    {
        int r0q = i0 * 64;
#pragma unroll
        for (int tp = 0; tp < 8; tp++) {
            int idx = tid + tp * 128;       // 0..1023
            int r = idx >> 4, cc = idx & 15;
            uint32_t so = (uint32_t)r * ARSB + (uint32_t)cc * 16u;
            size_t go = (size_t)(r0q + r) * HD + cc * 8;
            cp16(qhS + so, Qhp + go);
            cp16(qlS + so, Qlp + go);
        }
    }
    load_kv(kvb, Khp, Vhp, 0, tid);
    cp_commit();

    float oacc[16][4];
#pragma unroll
    for (int i = 0; i < 16; i++)
#pragma unroll
        for (int j = 0; j < 4; j++) oacc[i][j] = 0.f;
    float mA = -1e30f, mB = -1e30f, lA = 0.f, lB = 0.f;

    const int rowA = i0 * 64 + warpRow + t4;
    const int rowB = rowA + 8;
    const int nj = i0 + 1;

    for (int j = 0; j < nj; j++) {
        if (j + 1 < nj) {
            load_kv(kvb + ((j + 1) & 1) * KVSTG, Khp, Vhp, (j + 1) * 64, tid);
            cp_commit();
            cp_wait<1>();
        } else {
            cp_wait<0>();
        }
        __syncthreads();

        const uint32_t sb = kvb + (j & 1) * KVSTG;

        // ---- S = Q K^T (Q 2-term, K single) ----
        float sa[8][4];
#pragma unroll
        for (int nt = 0; nt < 8; nt++)
#pragma unroll
            for (int q = 0; q < 4; q++) sa[nt][q] = 0.f;

#pragma unroll
        for (int kp = 0; kp < 4; kp++) {
            uint32_t q0h[4], q1h[4], q0l[4], q1l[4];
            ldsm4(q0h, qhS + a_off + kp * 64);
            ldsm4(q1h, qhS + a_off + kp * 64 + 32);
            ldsm4(q0l, qlS + a_off + kp * 64);
            ldsm4(q1l, qlS + a_off + kp * 64 + 32);
#pragma unroll
            for (int nt = 0; nt < 8; nt++) {
                uint32_t kh[4];
                ldsm4(kh, sb + bk_off + nt * (8 * ARSB) + kp * 64);
                mma16816h(sa[nt], q0h, kh);
                mma16816h(sa[nt], q0l, kh);
                mma16816h(sa[nt], q1h, kh + 2);
                mma16816h(sa[nt], q1l, kh + 2);
            }
        }

        // ---- softcap + mask + online softmax ----
        float mxA = -1e30f, mxB = -1e30f;
#pragma unroll
        for (int nt = 0; nt < 8; nt++) {
            int c0 = j * 64 + nt * 8 + 2 * t2g;
            float v0 = softcap(sa[nt][0]);
            float v1 = softcap(sa[nt][1]);
            float v2 = softcap(sa[nt][2]);
            float v3 = softcap(sa[nt][3]);
            if (c0     > rowA) v0 = -1e30f;
            if (c0 + 1 > rowA) v1 = -1e30f;
            if (c0     > rowB) v2 = -1e30f;
            if (c0 + 1 > rowB) v3 = -1e30f;
            sa[nt][0] = v0; sa[nt][1] = v1; sa[nt][2] = v2; sa[nt][3] = v3;
            mxA = fmaxf(mxA, fmaxf(v0, v1));
            mxB = fmaxf(mxB, fmaxf(v2, v3));
        }
        mxA = fmaxf(mxA, __shfl_xor_sync(0xffffffffu, mxA, 1));
        mxA = fmaxf(mxA, __shfl_xor_sync(0xffffffffu, mxA, 2));
        mxB = fmaxf(mxB, __shfl_xor_sync(0xffffffffu, mxB, 1));
        mxB = fmaxf(mxB, __shfl_xor_sync(0xffffffffu, mxB, 2));

        float mAn = fmaxf(mA, mxA), mBn = fmaxf(mB, mxB);
        float fA = __expf(mA - mAn), fB = __expf(mB - mBn);
        mA = mAn; mB = mBn;

        float sA = 0.f, sB = 0.f;
#pragma unroll
        for (int nt = 0; nt < 8; nt++) {
            float p0 = __expf(sa[nt][0] - mA);
            float p1 = __expf(sa[nt][1] - mA);
            float p2 = __expf(sa[nt][2] - mB);
            float p3 = __expf(sa[nt][3] - mB);
            sa[nt][0] = p0; sa[nt][1] = p1; sa[nt][2] = p2; sa[nt][3] = p3;
            sA += p0 + p1; sB += p2 + p3;
        }
        sA += __shfl_xor_sync(0xffffffffu, sA, 1);
        sA += __shfl_xor_sync(0xffffffffu, sA, 2);
        sB += __shfl_xor_sync(0xffffffffu, sB, 1);
        sB += __shfl_xor_sync(0xffffffffu, sB, 2);
        lA = lA * fA + sA;
        lB = lB * fB + sB;
#pragma unroll
        for (int nt = 0; nt < 16; nt++) {
            oacc[nt][0] *= fA; oacc[nt][1] *= fA;
            oacc[nt][2] *= fB; oacc[nt][3] *= fB;
        }

        // ---- O += P V (P 2-term from registers, V single) ----
#pragma unroll
        for (int ks = 0; ks < 4; ks++) {
            uint32_t pah[4], pal[4];
            split2h(sa[2 * ks][0],     sa[2 * ks][1],     pah[0], pal[0]);
            split2h(sa[2 * ks][2],     sa[2 * ks][3],     pah[1], pal[1]);
            split2h(sa[2 * ks + 1][0], sa[2 * ks + 1][1], pah[2], pal[2]);
            split2h(sa[2 * ks + 1][2], sa[2 * ks + 1][3], pah[3], pal[3]);
#pragma unroll
            for (int ntp = 0; ntp < 8; ntp++) {
                uint32_t vh[4];
                ldsm4t(vh, sb + KVARR + v_off + ks * (16 * ARSB) + ntp * 32);
                mma16816h(oacc[2 * ntp],     pah, vh);
                mma16816h(oacc[2 * ntp],     pal, vh);
                mma16816h(oacc[2 * ntp + 1], pah, vh + 2);
                mma16816h(oacc[2 * ntp + 1], pal, vh + 2);
            }
        }
        __syncthreads();
    }

    // ---- epilogue: normalize, write g_Oh (fp16 single) [m][h*128+d] ----
    float invA = 1.f / lA, invB = 1.f / lB;
    size_t mAr = (size_t)b * 2048 + (size_t)rowA;   // rowA is global t
    size_t mBr = mAr + 8;
    int colbase = h * 128 + 2 * t2g;
#pragma unroll
    for (int nt = 0; nt < 16; nt++) {
        int c = colbase + nt * 8;
        *(uint32_t*)(g_Oh + mAr * 2048 + c) =
            pack2h(oacc[nt][0] * invA, oacc[nt][1] * invA);
        *(uint32_t*)(g_Oh + mBr * 2048 + c) =
            pack2h(oacc[nt][2] * invB, oacc[nt][3] * invB);
    }
}

// =====================================================================
// host entry
// =====================================================================
extern "C" void kernel_launch(void* const* d_in, const int* in_sizes, int n_in,
                              void* d_out, int out_size) {
    const float* x  = (const float*)d_in[0];
    // d_in[1] = mask (deterministic causal tril -> ignored)
    const float* qk = (const float*)d_in[2];
    const float* kk = (const float*)d_in[3];
    const float* vk = (const float*)d_in[4];
    const float* ok = (const float*)d_in[5];
    float* out = (float*)d_out;

    cudaFuncSetAttribute(gemm_f16<0>, cudaFuncAttributeMaxDynamicSharedMemorySize, SMEM_GEMM0);
    cudaFuncSetAttribute(gemm_f16<1>, cudaFuncAttributeMaxDynamicSharedMemorySize, SMEM_GEMM1);
    cudaFuncSetAttribute(attn_mma, cudaFuncAttributeMaxDynamicSharedMemorySize, SMEM_ATTN);

    // rope table + input conversion
    rope_tab<<<512, 256>>>();
    cvt_x<<<8192, 256>>>(x);
    cvt_w_all<<<dim3(192, 64), 256>>>(qk, kk, vk, ok);

    // fused QKV projection + rope epilogue (single-term A)
    gemm_f16<0><<<dim3(32, 32), 256, SMEM_GEMM0>>>(nullptr);

    // tensor-core flash attention (writes g_Oh fp16 single)
    attn_mma<<<dim3(TT / 64, TB * NH_Q), 128, SMEM_ATTN>>>();

    // output projection (single-term A)
    gemm_f16<1><<<dim3(16, 32), 256, SMEM_GEMM1>>>(out);
}